// round 5
// baseline (speedup 1.0000x reference)
#include <cuda_runtime.h>
#include <math.h>

// Problem constants
// B=8, CI=CO=64, H=W=256, M1=M2=16, G=4, NEXP=15, RANK=4, SCALING=0.1
#define NTOT (8*64*256*256)

// ---------------- scratch (device globals; no allocation allowed) ----------------
__device__ float  d_FW [256*128];       // forward W-DFT matrix  [w][2*ky + re/im]
__device__ float2 d_FH [128*256];       // forward H-DFT matrix  [kxIdx][h]
__device__ float2 d_FHI[256*128];       // inverse H matrix      [h][kxIdx]
__device__ float  d_FIW[128*256];       // inverse W matrix      [2*ky+c][w]  (1/(H*W) folded)
__device__ float  d_A  [512*256*128];   // stage1 out: [bc][h][2*ky+c]
__device__ float2 d_Xf [512*128*64];    // x_ft corners [bc][kxIdx][ky]
__device__ float2 d_Of [512*128*64];    // out_ft corners [bo][kxIdx][ky]
__device__ float  d_Z  [512*256*128];   // stage5 out: [bo][h][2*ky+c]
__device__ float2 d_wt [2*256*64*64];   // transposed base weights [t][p][i][o]
__device__ float2 d_lbt[2*15*256*4*64]; // transposed lora_b [t][e][p][r][o]
__device__ float2 d_la [2*15*4*64];     // lora_a complex [t][e][r][i]
__device__ float  d_gate[30];           // sigmoid(gate) [t*15+e]

// ---------------- packed fp32x2 helpers (FFMA2 — PTX-only on sm_103a) ----------------
#define FMAX2(acc, a, b) \
    asm("fma.rn.f32x2 %0, %1, %2, %0;" : "+l"(acc) : "l"(a), "l"(b))
#define PACK2(d, x, y) \
    asm("mov.b64 %0, {%1, %2};" : "=l"(d) : "f"(x), "f"(y))

__device__ __forceinline__ void cfma(float2& c, float2 a, float2 b) {
    c.x = fmaf(a.x, b.x, c.x); c.x = fmaf(-a.y, b.y, c.x);
    c.y = fmaf(a.x, b.y, c.y); c.y = fmaf( a.y, b.x, c.y);
}

// ---------------- init: trig tables (index reduced mod 256 -> exact periodicity) ------
__global__ void init_tables_k() {
    int id = blockIdx.x * 256 + threadIdx.x;
    const float STEP = 6.283185307179586f / 256.0f;
    if (id < 32768) {                       // FW
        int w = id >> 7, n = id & 127, ky = n >> 1;
        float ang = STEP * (float)((w * ky) & 255);
        d_FW[id] = (n & 1) ? -sinf(ang) : cosf(ang);
    } else if (id < 65536) {                // FH
        int r = id - 32768; int kxi = r >> 8, h = r & 255;
        int kx = (kxi < 64) ? kxi : kxi + 128;
        float ang = STEP * (float)((kx * h) & 255);
        d_FH[r] = make_float2(cosf(ang), -sinf(ang));
    } else if (id < 98304) {                // FHI
        int r = id - 65536; int h = r >> 7, kxi = r & 127;
        int kx = (kxi < 64) ? kxi : kxi + 128;
        float ang = STEP * (float)((kx * h) & 255);
        d_FHI[r] = make_float2(cosf(ang), sinf(ang));
    } else if (id < 131072) {               // FIW (1/65536 folded, Im(ky=0) row -> sin(0)=0)
        int r = id - 98304; int n = r >> 8, w = r & 255, k = n >> 1;
        float s = ((k == 0) ? 1.0f : 2.0f) * (1.0f / 65536.0f);
        float ang = STEP * (float)((k * w) & 255);
        d_FIW[r] = (n & 1) ? -s * sinf(ang) : s * cosf(ang);
    }
}

__global__ void init_wt_k(const float* __restrict__ w1re, const float* __restrict__ w1im,
                          const float* __restrict__ w2re, const float* __restrict__ w2im) {
    int id = blockIdx.x * 256 + threadIdx.x;
    if (id >= 2 * 256 * 4096) return;
    int t = id >> 20, rem = id & 1048575;
    int p = rem >> 12, io = rem & 4095;
    int i = io >> 6, o = io & 63;
    const float* re = t ? w2re : w1re;
    const float* im = t ? w2im : w1im;
    size_t src = ((size_t)(i * 64 + o)) * 256 + p;
    d_wt[id] = make_float2(re[src], im[src]);
}

__global__ void init_lbt_k(const float* __restrict__ b1re, const float* __restrict__ b1im,
                           const float* __restrict__ b2re, const float* __restrict__ b2im) {
    int id = blockIdx.x * 256 + threadIdx.x;
    if (id >= 2 * 15 * 256 * 256) return;
    int t = id / 983040, rem = id % 983040;
    int e = rem >> 16, rem2 = rem & 65535;
    int p = rem2 >> 8, ro = rem2 & 255;
    int r = ro >> 6, o = ro & 63;
    const float* re = t ? b2re : b1re;
    const float* im = t ? b2im : b1im;
    size_t src = (((size_t)(e * 64 + o)) * 4 + r) * 256 + p;
    d_lbt[id] = make_float2(re[src], im[src]);
}

__global__ void init_small_k(const float* __restrict__ la1re, const float* __restrict__ la1im,
                             const float* __restrict__ la2re, const float* __restrict__ la2im,
                             const float* __restrict__ g1, const float* __restrict__ g2,
                             float* sp_out) {
    int tid = threadIdx.x;
    for (int id = tid; id < 7680; id += 256) {
        int t = id / 3840, rem = id % 3840;
        const float* re = t ? la2re : la1re;
        const float* im = t ? la2im : la1im;
        d_la[id] = make_float2(re[rem], im[rem]);
    }
    __shared__ float gs[30];
    if (tid < 30) {
        float v = (tid < 15) ? g1[tid] : g2[tid - 15];
        float s = 1.0f / (1.0f + expf(-v));
        d_gate[tid] = s;
        gs[tid] = s;
    }
    __syncthreads();
    if (tid == 0 && sp_out) {
        float s = 0.0f;
        for (int i = 0; i < 30; i++) s += gs[i];
        *sp_out = s / 15.0f;
    }
}

// ---------------- fp32 SGEMM, packed f32x2 inner loop ----------------
// BM=128, BN=128, BK=16, 256 threads, 8x8 micro-tile (stored as 8x4 f32x2 pairs).
__global__ __launch_bounds__(256) void sgemm_k(const float* __restrict__ Amat,
                                               const float* __restrict__ Bmat,
                                               float* __restrict__ Cmat,
                                               int Kdim, int Ncols) {
    __shared__ float As[16][128];
    __shared__ float Bs[16][128];
    int tid = threadIdx.x;
    int m0 = blockIdx.x * 128, n0 = blockIdx.y * 128;
    int tx = tid & 15, ty = tid >> 4;
    unsigned long long accp[8][4] = {};   // zero bits == {0.0f, 0.0f}
    for (int k0 = 0; k0 < Kdim; k0 += 16) {
#pragma unroll
        for (int l = 0; l < 2; l++) {
            int flat = tid + l * 256;
            int row = flat >> 2, c4 = (flat & 3) * 4;
            float4 v = *(const float4*)(Amat + (size_t)(m0 + row) * Kdim + k0 + c4);
            As[c4 + 0][row] = v.x; As[c4 + 1][row] = v.y;
            As[c4 + 2][row] = v.z; As[c4 + 3][row] = v.w;
        }
#pragma unroll
        for (int l = 0; l < 2; l++) {
            int flat = tid + l * 256;
            int row = flat >> 5, c4 = (flat & 31) * 4;
            *(float4*)(&Bs[row][c4]) = *(const float4*)(Bmat + (size_t)(k0 + row) * Ncols + n0 + c4);
        }
        __syncthreads();
#pragma unroll
        for (int k = 0; k < 16; k++) {
            float4 a0 = *(const float4*)(&As[k][ty * 4]);
            float4 a1 = *(const float4*)(&As[k][64 + ty * 4]);
            unsigned long long ap[8];
            PACK2(ap[0], a0.x, a0.x); PACK2(ap[1], a0.y, a0.y);
            PACK2(ap[2], a0.z, a0.z); PACK2(ap[3], a0.w, a0.w);
            PACK2(ap[4], a1.x, a1.x); PACK2(ap[5], a1.y, a1.y);
            PACK2(ap[6], a1.z, a1.z); PACK2(ap[7], a1.w, a1.w);
            unsigned long long bp[4];
            bp[0] = *(const unsigned long long*)(&Bs[k][tx * 4]);
            bp[1] = *(const unsigned long long*)(&Bs[k][tx * 4 + 2]);
            bp[2] = *(const unsigned long long*)(&Bs[k][64 + tx * 4]);
            bp[3] = *(const unsigned long long*)(&Bs[k][64 + tx * 4 + 2]);
#pragma unroll
            for (int i = 0; i < 8; i++)
#pragma unroll
                for (int j = 0; j < 4; j++)
                    FMAX2(accp[i][j], ap[i], bp[j]);
        }
        __syncthreads();
    }
#pragma unroll
    for (int i = 0; i < 8; i++) {
        int m = m0 + ((i < 4) ? (ty * 4 + i) : (64 + ty * 4 + (i - 4)));
        float2 p0 = *(float2*)(&accp[i][0]);
        float2 p1 = *(float2*)(&accp[i][1]);
        float2 p2 = *(float2*)(&accp[i][2]);
        float2 p3 = *(float2*)(&accp[i][3]);
        float4 v0 = {p0.x, p0.y, p1.x, p1.y};
        float4 v1 = {p2.x, p2.y, p3.x, p3.y};
        *(float4*)(Cmat + (size_t)m * Ncols + n0 + tx * 4)      = v0;
        *(float4*)(Cmat + (size_t)m * Ncols + n0 + 64 + tx * 4) = v1;
    }
}

// ---------------- batched complex GEMM, packed f32x2 inner loop ----------------
// C[bat][M,64] = F[M,K] (shared across batch) * Bm[bat][K,64]
// BM=64, BN=64, BK=16, 256 threads, 4x4 complex micro-tile.
// Complex MAC: acc{re,im} += {f.x,f.x}*{b.x,b.y} + {f.y,f.y}*{-b.y,b.x}
__global__ __launch_bounds__(256) void cgemm_k(const float2* __restrict__ F,
                                               const float2* __restrict__ Bm,
                                               float2* __restrict__ Cm,
                                               int Mdim, int Kdim) {
    int bat = blockIdx.x;
    int m0 = blockIdx.y * 64;
    const float2* Bb = Bm + (size_t)bat * Kdim * 64;
    float2* Cb = Cm + (size_t)bat * Mdim * 64;
    __shared__ float2 Fs[16][64];
    __shared__ float2 Bs[16][64];
    __shared__ float2 Bw[16][64];   // negated-swapped copy {-im, re}
    int tid = threadIdx.x;
    int tx = tid & 15, ty = tid >> 4;
    unsigned long long acc[4][4] = {};
    for (int k0 = 0; k0 < Kdim; k0 += 16) {
#pragma unroll
        for (int l = 0; l < 2; l++) {
            int flat = tid + l * 256;
            int row = flat >> 3, c = flat & 7;
            float4 v = *(const float4*)(F + (size_t)(m0 + row) * Kdim + k0 + c * 2);
            Fs[c * 2][row]     = make_float2(v.x, v.y);
            Fs[c * 2 + 1][row] = make_float2(v.z, v.w);
        }
#pragma unroll
        for (int l = 0; l < 2; l++) {
            int flat = tid + l * 256;
            int row = flat >> 5, c = flat & 31;
            float4 v = *(const float4*)(Bb + (size_t)(k0 + row) * 64 + c * 2);
            Bs[row][c * 2]     = make_float2(v.x, v.y);
            Bs[row][c * 2 + 1] = make_float2(v.z, v.w);
            Bw[row][c * 2]     = make_float2(-v.y, v.x);
            Bw[row][c * 2 + 1] = make_float2(-v.w, v.z);
        }
        __syncthreads();
#pragma unroll
        for (int k = 0; k < 16; k++) {
            float4 f01 = *(const float4*)(&Fs[k][ty * 4]);
            float4 f23 = *(const float4*)(&Fs[k][ty * 4 + 2]);
            unsigned long long fx[4], fy[4];
            PACK2(fx[0], f01.x, f01.x); PACK2(fy[0], f01.y, f01.y);
            PACK2(fx[1], f01.z, f01.z); PACK2(fy[1], f01.w, f01.w);
            PACK2(fx[2], f23.x, f23.x); PACK2(fy[2], f23.y, f23.y);
            PACK2(fx[3], f23.z, f23.z); PACK2(fy[3], f23.w, f23.w);
            unsigned long long bp[4], bw[4];
#pragma unroll
            for (int j = 0; j < 4; j++) {
                bp[j] = *(const unsigned long long*)(&Bs[k][tx * 4 + j]);
                bw[j] = *(const unsigned long long*)(&Bw[k][tx * 4 + j]);
            }
#pragma unroll
            for (int i = 0; i < 4; i++)
#pragma unroll
                for (int j = 0; j < 4; j++) {
                    FMAX2(acc[i][j], fx[i], bp[j]);
                    FMAX2(acc[i][j], fy[i], bw[j]);
                }
        }
        __syncthreads();
    }
#pragma unroll
    for (int i = 0; i < 4; i++) {
        int m = m0 + ty * 4 + i;
#pragma unroll
        for (int j = 0; j < 4; j += 2) {
            float2 p0 = *(float2*)(&acc[i][j]);
            float2 p1 = *(float2*)(&acc[i][j + 1]);
            float4 v = {p0.x, p0.y, p1.x, p1.y};
            *(float4*)(Cb + (size_t)m * 64 + tx * 4 + j) = v;
        }
    }
}

// ---------------- base tiles: Of[b,o,p] = sum_i Xf[b,i,p] * w[i,o,p] ----------------
__global__ __launch_bounds__(512) void base_mul_k() {
    int t = blockIdx.x;
    int p = blockIdx.y;
    int x = p >> 4, y = p & 15;
    int kxIdx = (t == 0) ? x : (112 + x);
    int ky = y;
    __shared__ float2 Xs[8][64];
    int tid = threadIdx.x;
    {
        int b = tid >> 6, i = tid & 63;
        Xs[b][i] = d_Xf[(size_t)(b * 64 + i) * 8192 + kxIdx * 64 + ky];
    }
    __syncthreads();
    int o = tid & 63, b = tid >> 6;
    const float2* wp = d_wt + ((size_t)t * 256 + p) * 4096;
    float2 s = {0.0f, 0.0f};
#pragma unroll 8
    for (int i = 0; i < 64; i++) {
        float2 w = wp[i * 64 + o];
        cfma(s, Xs[b][i], w);
    }
    d_Of[(size_t)(b * 64 + o) * 8192 + kxIdx * 64 + ky] = s;
}

// ---------------- expert tiles via LoRA factorization ----------------
__global__ __launch_bounds__(512) void expert_mul_k() {
    int tile = blockIdx.x;
    int half = tile / 15, e = tile % 15;
    int p = blockIdx.y;
    int x = p >> 4, y = p & 15;
    int Rr = (e + 1) >> 2, Cc = (e + 1) & 3;
    int ky = Cc * 16 + y;
    int kxIdx = (half == 0) ? (Rr * 16 + x) : (64 + (3 - Rr) * 16 + x);
    __shared__ float2 Xs[8][64];
    __shared__ float2 Ts[8][4];
    int tid = threadIdx.x;
    {
        int b = tid >> 6, i = tid & 63;
        Xs[b][i] = d_Xf[(size_t)(b * 64 + i) * 8192 + kxIdx * 64 + ky];
    }
    __syncthreads();
    if (tid < 32) {
        int b = tid >> 2, r = tid & 3;
        const float2* lap = d_la + (size_t)(half * 15 + e) * 256 + r * 64;
        float2 s = {0.0f, 0.0f};
#pragma unroll 8
        for (int i = 0; i < 64; i++) cfma(s, Xs[b][i], lap[i]);
        Ts[b][r] = s;
    }
    __syncthreads();
    int o = tid & 63, b = tid >> 6;
    const float2* lbp = d_lbt + ((size_t)(half * 15 + e) * 256 + p) * 256;
    float2 s = {0.0f, 0.0f};
#pragma unroll
    for (int r = 0; r < 4; r++) {
        float2 w = lbp[r * 64 + o];
        cfma(s, Ts[b][r], w);
    }
    float g = d_gate[half * 15 + e] * 0.1f;
    s.x *= g; s.y *= g;
    d_Of[(size_t)(b * 64 + o) * 8192 + kxIdx * 64 + ky] = s;
}

// ---------------------------------- launch ----------------------------------
extern "C" void kernel_launch(void* const* d_in, const int* in_sizes, int n_in,
                              void* d_out, int out_size) {
    const float* x     = (const float*)d_in[0];
    const float* w1re  = (const float*)d_in[1];
    const float* w1im  = (const float*)d_in[2];
    const float* w2re  = (const float*)d_in[3];
    const float* w2im  = (const float*)d_in[4];
    const float* la1re = (const float*)d_in[5];
    const float* la1im = (const float*)d_in[6];
    const float* lb1re = (const float*)d_in[7];
    const float* lb1im = (const float*)d_in[8];
    const float* la2re = (const float*)d_in[9];
    const float* la2im = (const float*)d_in[10];
    const float* lb2re = (const float*)d_in[11];
    const float* lb2im = (const float*)d_in[12];
    const float* g1    = (const float*)d_in[13];
    const float* g2    = (const float*)d_in[14];
    float* out = (float*)d_out;

    void *pA, *pZ, *pXf, *pOf, *pFW, *pFH, *pFHI, *pFIW;
    cudaGetSymbolAddress(&pA, d_A);
    cudaGetSymbolAddress(&pZ, d_Z);
    cudaGetSymbolAddress(&pXf, d_Xf);
    cudaGetSymbolAddress(&pOf, d_Of);
    cudaGetSymbolAddress(&pFW, d_FW);
    cudaGetSymbolAddress(&pFH, d_FH);
    cudaGetSymbolAddress(&pFHI, d_FHI);
    cudaGetSymbolAddress(&pFIW, d_FIW);

    float* sp_out = (out_size > NTOT) ? (out + NTOT) : nullptr;

    init_tables_k<<<512, 256>>>();
    init_wt_k<<<8192, 256>>>(w1re, w1im, w2re, w2im);
    init_lbt_k<<<7680, 256>>>(lb1re, lb1im, lb2re, lb2im);
    init_small_k<<<1, 256>>>(la1re, la1im, la2re, la2im, g1, g2, sp_out);

    // K1: A[bc*h][2ky+c] = x[bc*h][w] * FW[w][2ky+c]
    sgemm_k<<<dim3(1024, 1), 256>>>(x, (const float*)pFW, (float*)pA, 256, 128);
    // K2: Xf[bc][kxIdx][ky] = FH[kxIdx][h] * A[bc][h][ky]
    cgemm_k<<<dim3(512, 2), 256>>>((const float2*)pFH, (const float2*)pA, (float2*)pXf, 128, 256);
    // spectral multiply
    base_mul_k<<<dim3(2, 256), 512>>>();
    expert_mul_k<<<dim3(30, 256), 512>>>();
    // K5: Z[bo][h][ky] = FHI[h][kxIdx] * Of[bo][kxIdx][ky]
    cgemm_k<<<dim3(512, 4), 256>>>((const float2*)pFHI, (const float2*)pOf, (float2*)pZ, 256, 128);
    // K6: y[bo*h][w] = Z[bo*h][2ky+c] * FIW[2ky+c][w]
    sgemm_k<<<dim3(1024, 2), 256>>>((const float*)pZ, (const float*)pFIW, out, 128, 256);
}

// round 6
// speedup vs baseline: 1.2215x; 1.2215x over previous
#include <cuda_runtime.h>
#include <math.h>

#define NTOT (8*64*256*256)

// ---------------- scratch ----------------
__device__ float  d_XE [131072*144];
__device__ float  d_XO [131072*128];
__device__ float  d_ARe[131072*64];
__device__ float  d_AIm[131072*64];
__device__ float2 d_SA [512*144*64];
__device__ float2 d_DA [512*144*64];
__device__ float2 d_Xf [512*128*64];
__device__ float2 d_Of [512*128*64];
__device__ float2 d_SO [512*80*64];
__device__ float2 d_DO [512*80*64];
__device__ float  d_Zre[131072*64];
__device__ float  d_Zim[131072*64];
__device__ float  d_T1RE[144*64];
__device__ float  d_T1IM[128*64];
__device__ float2 d_FHf [128*144];
__device__ float2 d_FHIf[256*80];
__device__ float  d_TC [64*128];
__device__ float  d_TS [64*128];
__device__ float2 d_wt [2*256*64*64];
__device__ float2 d_lbt[2*15*256*4*64];
__device__ float2 d_la [2*15*4*64];
__device__ float  d_gate[30];

__device__ __forceinline__ void cfma(float2& c, float2 a, float2 b) {
    c.x = fmaf(a.x, b.x, c.x); c.x = fmaf(-a.y, b.y, c.x);
    c.y = fmaf(a.x, b.y, c.y); c.y = fmaf( a.y, b.x, c.y);
}

// ---------------- tables ----------------
__global__ void init_tabs_k() {
    int id = blockIdx.x * 256 + threadIdx.x;
    const float S = 6.283185307179586f / 256.0f;
    if (id < 9216) {                        // T1RE [144][64]
        int s = id >> 6, ky = id & 63; float v = 0.f;
        if (s == 0) v = 1.f;
        else if (s == 1) v = (ky & 1) ? -1.f : 1.f;
        else if (s <= 128) v = cosf(S * (float)(((s - 1) * ky) & 255));
        d_T1RE[id] = v;
    } else if (id < 17408) {                // T1IM [128][64]
        int r = id - 9216, s = r >> 6, ky = r & 63; float v = 0.f;
        if (s <= 126) v = -sinf(S * (float)(((s + 1) * ky) & 255));
        d_T1IM[r] = v;
    } else if (id < 35840) {                // FHf [128][144] (cos,sin)
        int r = id - 17408, m = r / 144, hp = r % 144;
        float2 v = make_float2(0.f, 0.f);
        if (hp <= 128) {
            int kx = (m < 64) ? m : m + 128;
            float a = S * (float)((kx * hp) & 255);
            v = make_float2(cosf(a), sinf(a));
        }
        d_FHf[r] = v;
    } else if (id < 56320) {                // FHIf [256][80]
        int r = id - 35840, h = r / 80, kk = r % 80;
        float2 v = make_float2(0.f, 0.f);
        if (kk <= 64) {
            int ke = (kk == 64) ? 192 : kk;
            float a = S * (float)((ke * h) & 255);
            v = make_float2(cosf(a), sinf(a));
        }
        d_FHIf[r] = v;
    } else if (id < 64512) {                // TC [64][128]
        int r = id - 56320, ky = r >> 7, w = r & 127;
        float sc = ((ky == 0) ? 1.f : 2.f) * (1.f / 65536.f);
        d_TC[r] = sc * cosf(S * (float)((ky * w) & 255));
    } else if (id < 72704) {                // TS [64][128]
        int r = id - 64512, ky = r >> 7, w = r & 127;
        float sc = ((ky == 0) ? 1.f : 2.f) * (1.f / 65536.f);
        d_TS[r] = sc * sinf(S * (float)((ky * w) & 255));
    }
}

__global__ void init_wt_k(const float* __restrict__ w1re, const float* __restrict__ w1im,
                          const float* __restrict__ w2re, const float* __restrict__ w2im) {
    int id = blockIdx.x * 256 + threadIdx.x;
    if (id >= 2 * 256 * 4096) return;
    int t = id >> 20, rem = id & 1048575;
    int p = rem >> 12, io = rem & 4095;
    int i = io >> 6, o = io & 63;
    const float* re = t ? w2re : w1re;
    const float* im = t ? w2im : w1im;
    size_t src = ((size_t)(i * 64 + o)) * 256 + p;
    d_wt[id] = make_float2(re[src], im[src]);
}

__global__ void init_lbt_k(const float* __restrict__ b1re, const float* __restrict__ b1im,
                           const float* __restrict__ b2re, const float* __restrict__ b2im) {
    int id = blockIdx.x * 256 + threadIdx.x;
    if (id >= 2 * 15 * 256 * 256) return;
    int t = id / 983040, rem = id % 983040;
    int e = rem >> 16, rem2 = rem & 65535;
    int p = rem2 >> 8, ro = rem2 & 255;
    int r = ro >> 6, o = ro & 63;
    const float* re = t ? b2re : b1re;
    const float* im = t ? b2im : b1im;
    size_t src = (((size_t)(e * 64 + o)) * 4 + r) * 256 + p;
    d_lbt[id] = make_float2(re[src], im[src]);
}

__global__ void init_small_k(const float* __restrict__ la1re, const float* __restrict__ la1im,
                             const float* __restrict__ la2re, const float* __restrict__ la2im,
                             const float* __restrict__ g1, const float* __restrict__ g2,
                             float* sp_out) {
    int tid = threadIdx.x;
    for (int id = tid; id < 7680; id += 256) {
        int t = id / 3840, rem = id % 3840;
        const float* re = t ? la2re : la1re;
        const float* im = t ? la2im : la1im;
        d_la[id] = make_float2(re[rem], im[rem]);
    }
    __shared__ float gs[30];
    if (tid < 30) {
        float v = (tid < 15) ? g1[tid] : g2[tid - 15];
        float s = 1.0f / (1.0f + expf(-v));
        d_gate[tid] = s; gs[tid] = s;
    }
    __syncthreads();
    if (tid == 0 && sp_out) {
        float s = 0.0f;
        for (int i = 0; i < 30; i++) s += gs[i];
        *sp_out = s / 15.0f;
    }
}

// ---------------- fold passes ----------------
__global__ void fold_x_k(const float* __restrict__ x) {
    int m = blockIdx.x, w = threadIdx.x;     // 128 threads
    const float* xr = x + (size_t)m * 256;
    float* xe = d_XE + (size_t)m * 144;
    float* xo = d_XO + (size_t)m * 128;
    if (w == 0) {
        xe[0] = xr[0]; xe[1] = xr[128]; xo[127] = 0.f;
    } else {
        float a = xr[w], b = xr[256 - w];
        xe[w + 1] = a + b; xo[w - 1] = a - b;
    }
    if (w < 15) xe[129 + w] = 0.f;
}

__global__ void fold_A_k() {
    int id = blockIdx.x * 256 + threadIdx.x;       // 512*144*64
    int ky = id & 63, r = id >> 6;
    int hp = r % 144, bc = r / 144;
    size_t base = (size_t)bc * 16384 + ky;         // 256*64
    float2 Sv, Dv;
    if (hp == 0)        { Sv = make_float2(d_ARe[base], d_AIm[base]); Dv = make_float2(0.f, 0.f); }
    else if (hp == 128) { size_t q = base + 128 * 64; Sv = make_float2(d_ARe[q], d_AIm[q]); Dv = make_float2(0.f, 0.f); }
    else if (hp < 128) {
        size_t p = base + (size_t)hp * 64, q = base + (size_t)(256 - hp) * 64;
        float pr = d_ARe[p], pi = d_AIm[p], qr = d_ARe[q], qi = d_AIm[q];
        Sv = make_float2(pr + qr, pi + qi); Dv = make_float2(pr - qr, pi - qi);
    } else { Sv = make_float2(0.f, 0.f); Dv = Sv; }
    d_SA[id] = Sv; d_DA[id] = Dv;
}

__global__ void fold_Of_k() {
    int id = blockIdx.x * 256 + threadIdx.x;       // 512*80*64
    int ky = id & 63, r = id >> 6;
    int kk = r % 80, bc = r / 80;
    const float2* Ob = d_Of + (size_t)bc * 8192;
    float2 Sv, Dv;
    if (kk == 0) { Sv = Ob[ky]; Dv = make_float2(0.f, 0.f); }
    else if (kk < 64) {
        float2 p = Ob[kk * 64 + ky], q = Ob[(128 - kk) * 64 + ky];
        Sv = make_float2(p.x + q.x, p.y + q.y); Dv = make_float2(p.x - q.x, p.y - q.y);
    } else if (kk == 64) { Sv = Ob[64 * 64 + ky]; Dv = Sv; }
    else { Sv = make_float2(0.f, 0.f); Dv = Sv; }
    d_SO[id] = Sv; d_DO[id] = Dv;
}

// ---------------- real GEMM N=64: C[m][64] = A[m][K] * B[K][64] ----------------
__global__ __launch_bounds__(256) void sgemm64_k(const float* __restrict__ A,
                                                 const float* __restrict__ B,
                                                 float* __restrict__ C, int Kdim) {
    __shared__ float As[16][128];
    __shared__ float Bs[16][64];
    int tid = threadIdx.x, m0 = blockIdx.x * 128;
    int tx = tid & 15, ty = tid >> 4;
    float acc[8][4] = {};
    for (int k0 = 0; k0 < Kdim; k0 += 16) {
#pragma unroll
        for (int l = 0; l < 2; l++) {
            int f = tid + l * 256, row = f >> 2, c4 = (f & 3) * 4;
            float4 v = *(const float4*)(A + (size_t)(m0 + row) * Kdim + k0 + c4);
            As[c4][row] = v.x; As[c4 + 1][row] = v.y; As[c4 + 2][row] = v.z; As[c4 + 3][row] = v.w;
        }
        {
            int row = tid >> 4, c4 = (tid & 15) * 4;
            *(float4*)(&Bs[row][c4]) = *(const float4*)(B + (k0 + row) * 64 + c4);
        }
        __syncthreads();
#pragma unroll
        for (int k = 0; k < 16; k++) {
            float a[8], b[4];
#pragma unroll
            for (int i = 0; i < 4; i++) { a[i] = As[k][ty * 4 + i]; a[4 + i] = As[k][64 + ty * 4 + i]; }
#pragma unroll
            for (int j = 0; j < 4; j++) b[j] = Bs[k][tx * 4 + j];
#pragma unroll
            for (int i = 0; i < 8; i++)
#pragma unroll
                for (int j = 0; j < 4; j++)
                    acc[i][j] = fmaf(a[i], b[j], acc[i][j]);
        }
        __syncthreads();
    }
#pragma unroll
    for (int i = 0; i < 8; i++) {
        int m = m0 + ((i < 4) ? (ty * 4 + i) : (64 + ty * 4 + (i - 4)));
        float4 v = {acc[i][0], acc[i][1], acc[i][2], acc[i][3]};
        *(float4*)(C + (size_t)m * 64 + tx * 4) = v;
    }
}

// ---------------- folded "complex" GEMM ----------------
// acc.x += S.x*c + SGN*D.y*s ; acc.y += S.y*c - SGN*D.x*s     (c,s) = F[m][k]
template<int SGN, int SPLIT>
__global__ __launch_bounds__(256) void cgemm_fold_k(const float2* __restrict__ F,
        const float2* __restrict__ Sp, const float2* __restrict__ Dp,
        float2* __restrict__ Cc, float* __restrict__ Cre, float* __restrict__ Cim,
        int Kdim, int Mdim) {
    int bat = blockIdx.x, m0 = blockIdx.y * 64;
    const float2* Sb = Sp + (size_t)bat * Kdim * 64;
    const float2* Db = Dp + (size_t)bat * Kdim * 64;
    __shared__ float2 Fs[16][64], Ss[16][64], Ds[16][64];
    int tid = threadIdx.x, tx = tid & 15, ty = tid >> 4;
    float2 acc[4][4] = {};
    for (int k0 = 0; k0 < Kdim; k0 += 16) {
#pragma unroll
        for (int l = 0; l < 2; l++) {
            int f = tid + l * 256, row = f >> 3, c = f & 7;
            float4 v = *(const float4*)(F + (size_t)(m0 + row) * Kdim + k0 + 2 * c);
            Fs[2 * c][row]     = make_float2(v.x, v.y);
            Fs[2 * c + 1][row] = make_float2(v.z, v.w);
        }
#pragma unroll
        for (int l = 0; l < 2; l++) {
            int f = tid + l * 256, row = f >> 5, c = f & 31;
            *(float4*)(&Ss[row][2 * c]) = *(const float4*)(Sb + (size_t)(k0 + row) * 64 + 2 * c);
            *(float4*)(&Ds[row][2 * c]) = *(const float4*)(Db + (size_t)(k0 + row) * 64 + 2 * c);
        }
        __syncthreads();
#pragma unroll
        for (int k = 0; k < 16; k++) {
            float2 fv[4], sv[4], dv[4];
#pragma unroll
            for (int i = 0; i < 4; i++) fv[i] = Fs[k][ty * 4 + i];
#pragma unroll
            for (int j = 0; j < 4; j++) { sv[j] = Ss[k][tx * 4 + j]; dv[j] = Ds[k][tx * 4 + j]; }
#pragma unroll
            for (int i = 0; i < 4; i++)
#pragma unroll
                for (int j = 0; j < 4; j++) {
                    acc[i][j].x = fmaf(sv[j].x, fv[i].x, acc[i][j].x);
                    acc[i][j].x = fmaf((SGN > 0) ? dv[j].y : -dv[j].y, fv[i].y, acc[i][j].x);
                    acc[i][j].y = fmaf(sv[j].y, fv[i].x, acc[i][j].y);
                    acc[i][j].y = fmaf((SGN > 0) ? -dv[j].x : dv[j].x, fv[i].y, acc[i][j].y);
                }
        }
        __syncthreads();
    }
    if (SPLIT) {
        float* Rb = Cre + (size_t)bat * Mdim * 64;
        float* Ib = Cim + (size_t)bat * Mdim * 64;
#pragma unroll
        for (int i = 0; i < 4; i++) {
            int m = m0 + ty * 4 + i;
            float4 vr = {acc[i][0].x, acc[i][1].x, acc[i][2].x, acc[i][3].x};
            float4 vi = {acc[i][0].y, acc[i][1].y, acc[i][2].y, acc[i][3].y};
            *(float4*)(Rb + (size_t)m * 64 + tx * 4) = vr;
            *(float4*)(Ib + (size_t)m * 64 + tx * 4) = vi;
        }
    } else {
        float2* Cb = Cc + (size_t)bat * Mdim * 64;
#pragma unroll
        for (int i = 0; i < 4; i++) {
            int m = m0 + ty * 4 + i;
#pragma unroll
            for (int j = 0; j < 4; j += 2) {
                float4 v = {acc[i][j].x, acc[i][j].y, acc[i][j + 1].x, acc[i][j + 1].y};
                *(float4*)(Cb + (size_t)m * 64 + tx * 4 + j) = v;
            }
        }
    }
}

// ---------------- spectral multiply (unchanged) ----------------
__global__ __launch_bounds__(512) void base_mul_k() {
    int t = blockIdx.x, p = blockIdx.y;
    int x = p >> 4, y = p & 15;
    int kxIdx = (t == 0) ? x : (112 + x);
    int ky = y;
    __shared__ float2 Xs[8][64];
    int tid = threadIdx.x;
    {
        int b = tid >> 6, i = tid & 63;
        Xs[b][i] = d_Xf[(size_t)(b * 64 + i) * 8192 + kxIdx * 64 + ky];
    }
    __syncthreads();
    int o = tid & 63, b = tid >> 6;
    const float2* wp = d_wt + ((size_t)t * 256 + p) * 4096;
    float2 s = {0.f, 0.f};
#pragma unroll 8
    for (int i = 0; i < 64; i++) cfma(s, Xs[b][i], wp[i * 64 + o]);
    d_Of[(size_t)(b * 64 + o) * 8192 + kxIdx * 64 + ky] = s;
}

__global__ __launch_bounds__(512) void expert_mul_k() {
    int tile = blockIdx.x;
    int half = tile / 15, e = tile % 15;
    int p = blockIdx.y;
    int x = p >> 4, y = p & 15;
    int Rr = (e + 1) >> 2, Cc = (e + 1) & 3;
    int ky = Cc * 16 + y;
    int kxIdx = (half == 0) ? (Rr * 16 + x) : (64 + (3 - Rr) * 16 + x);
    __shared__ float2 Xs[8][64];
    __shared__ float2 Ts[8][4];
    int tid = threadIdx.x;
    {
        int b = tid >> 6, i = tid & 63;
        Xs[b][i] = d_Xf[(size_t)(b * 64 + i) * 8192 + kxIdx * 64 + ky];
    }
    __syncthreads();
    if (tid < 32) {
        int b = tid >> 2, r = tid & 3;
        const float2* lap = d_la + (size_t)(half * 15 + e) * 256 + r * 64;
        float2 s = {0.f, 0.f};
#pragma unroll 8
        for (int i = 0; i < 64; i++) cfma(s, Xs[b][i], lap[i]);
        Ts[b][r] = s;
    }
    __syncthreads();
    int o = tid & 63, b = tid >> 6;
    const float2* lbp = d_lbt + ((size_t)(half * 15 + e) * 256 + p) * 256;
    float2 s = {0.f, 0.f};
#pragma unroll
    for (int r = 0; r < 4; r++) cfma(s, Ts[b][r], lbp[r * 64 + o]);
    float g = d_gate[half * 15 + e] * 0.1f;
    s.x *= g; s.y *= g;
    d_Of[(size_t)(b * 64 + o) * 8192 + kxIdx * 64 + ky] = s;
}

// ---------------- K6: fused irfft-W with w-fold ----------------
__global__ __launch_bounds__(256) void k6_k(float* __restrict__ out) {
    __shared__ float Rs[16][128], Is[16][128], Cs[16][64], Sn[16][64];
    int tid = threadIdx.x, m0 = blockIdx.x * 128, n0 = blockIdx.y * 64;
    int tx = tid & 15, ty = tid >> 4;
    float accP[8][4] = {}, accQ[8][4] = {};
    for (int k0 = 0; k0 < 64; k0 += 16) {
#pragma unroll
        for (int l = 0; l < 2; l++) {
            int f = tid + l * 256, row = f >> 2, c4 = (f & 3) * 4;
            float4 v = *(const float4*)(d_Zre + (size_t)(m0 + row) * 64 + k0 + c4);
            Rs[c4][row] = v.x; Rs[c4 + 1][row] = v.y; Rs[c4 + 2][row] = v.z; Rs[c4 + 3][row] = v.w;
            float4 u = *(const float4*)(d_Zim + (size_t)(m0 + row) * 64 + k0 + c4);
            Is[c4][row] = u.x; Is[c4 + 1][row] = u.y; Is[c4 + 2][row] = u.z; Is[c4 + 3][row] = u.w;
        }
        {
            int row = tid >> 4, c4 = (tid & 15) * 4;
            *(float4*)(&Cs[row][c4]) = *(const float4*)(d_TC + (k0 + row) * 128 + n0 + c4);
            *(float4*)(&Sn[row][c4]) = *(const float4*)(d_TS + (k0 + row) * 128 + n0 + c4);
        }
        __syncthreads();
#pragma unroll
        for (int k = 0; k < 16; k++) {
            float ar[8], ai[8], bc[4], bs[4];
#pragma unroll
            for (int i = 0; i < 4; i++) {
                ar[i] = Rs[k][ty * 4 + i]; ar[4 + i] = Rs[k][64 + ty * 4 + i];
                ai[i] = Is[k][ty * 4 + i]; ai[4 + i] = Is[k][64 + ty * 4 + i];
            }
#pragma unroll
            for (int j = 0; j < 4; j++) { bc[j] = Cs[k][tx * 4 + j]; bs[j] = Sn[k][tx * 4 + j]; }
#pragma unroll
            for (int i = 0; i < 8; i++)
#pragma unroll
                for (int j = 0; j < 4; j++) {
                    accP[i][j] = fmaf(ar[i], bc[j], accP[i][j]);
                    accQ[i][j] = fmaf(ai[i], bs[j], accQ[i][j]);
                }
        }
        __syncthreads();
    }
#pragma unroll
    for (int i = 0; i < 8; i++) {
        int m = m0 + ((i < 4) ? (ty * 4 + i) : (64 + ty * 4 + (i - 4)));
        int w = n0 + tx * 4;
        float4 v = {accP[i][0] - accQ[i][0], accP[i][1] - accQ[i][1],
                    accP[i][2] - accQ[i][2], accP[i][3] - accQ[i][3]};
        *(float4*)(out + (size_t)m * 256 + w) = v;
#pragma unroll
        for (int j = 0; j < 4; j++) {
            int wj = w + j;
            if (wj > 0) out[(size_t)m * 256 + 256 - wj] = accP[i][j] + accQ[i][j];
        }
    }
}

__global__ void y128_k(float* __restrict__ out) {
    int m = blockIdx.x * 256 + threadIdx.x;
    const float* z = d_Zre + (size_t)m * 64;
    float s = z[0] * (1.f / 65536.f);
#pragma unroll 8
    for (int k = 1; k < 64; k++)
        s = fmaf(z[k], ((k & 1) ? -2.f : 2.f) * (1.f / 65536.f), s);
    out[(size_t)m * 256 + 128] = s;
}

// ---------------------------------- launch ----------------------------------
extern "C" void kernel_launch(void* const* d_in, const int* in_sizes, int n_in,
                              void* d_out, int out_size) {
    const float* x     = (const float*)d_in[0];
    const float* w1re  = (const float*)d_in[1];
    const float* w1im  = (const float*)d_in[2];
    const float* w2re  = (const float*)d_in[3];
    const float* w2im  = (const float*)d_in[4];
    const float* la1re = (const float*)d_in[5];
    const float* la1im = (const float*)d_in[6];
    const float* lb1re = (const float*)d_in[7];
    const float* lb1im = (const float*)d_in[8];
    const float* la2re = (const float*)d_in[9];
    const float* la2im = (const float*)d_in[10];
    const float* lb2re = (const float*)d_in[11];
    const float* lb2im = (const float*)d_in[12];
    const float* g1    = (const float*)d_in[13];
    const float* g2    = (const float*)d_in[14];
    float* out = (float*)d_out;

    void *pXE, *pXO, *pARe, *pAIm, *pT1RE, *pT1IM, *pFHf, *pFHIf;
    void *pSA, *pDA, *pXf, *pSO, *pDO, *pZre, *pZim;
    cudaGetSymbolAddress(&pXE, d_XE);     cudaGetSymbolAddress(&pXO, d_XO);
    cudaGetSymbolAddress(&pARe, d_ARe);   cudaGetSymbolAddress(&pAIm, d_AIm);
    cudaGetSymbolAddress(&pT1RE, d_T1RE); cudaGetSymbolAddress(&pT1IM, d_T1IM);
    cudaGetSymbolAddress(&pFHf, d_FHf);   cudaGetSymbolAddress(&pFHIf, d_FHIf);
    cudaGetSymbolAddress(&pSA, d_SA);     cudaGetSymbolAddress(&pDA, d_DA);
    cudaGetSymbolAddress(&pXf, d_Xf);
    cudaGetSymbolAddress(&pSO, d_SO);     cudaGetSymbolAddress(&pDO, d_DO);
    cudaGetSymbolAddress(&pZre, d_Zre);   cudaGetSymbolAddress(&pZim, d_Zim);

    float* sp_out = (out_size > NTOT) ? (out + NTOT) : nullptr;

    init_tabs_k<<<288, 256>>>();
    init_wt_k<<<8192, 256>>>(w1re, w1im, w2re, w2im);
    init_lbt_k<<<7680, 256>>>(lb1re, lb1im, lb2re, lb2im);
    init_small_k<<<1, 256>>>(la1re, la1im, la2re, la2im, g1, g2, sp_out);

    fold_x_k<<<131072, 128>>>(x);
    sgemm64_k<<<1024, 256>>>((const float*)pXE, (const float*)pT1RE, (float*)pARe, 144);
    sgemm64_k<<<1024, 256>>>((const float*)pXO, (const float*)pT1IM, (float*)pAIm, 128);
    fold_A_k<<<18432, 256>>>();
    cgemm_fold_k<1, 0><<<dim3(512, 2), 256>>>((const float2*)pFHf, (const float2*)pSA,
        (const float2*)pDA, (float2*)pXf, nullptr, nullptr, 144, 128);
    base_mul_k<<<dim3(2, 256), 512>>>();
    expert_mul_k<<<dim3(30, 256), 512>>>();
    fold_Of_k<<<10240, 256>>>();
    cgemm_fold_k<-1, 1><<<dim3(512, 4), 256>>>((const float2*)pFHIf, (const float2*)pSO,
        (const float2*)pDO, nullptr, (float*)pZre, (float*)pZim, 80, 256);
    k6_k<<<dim3(1024, 2), 256>>>(out);
    y128_k<<<512, 256>>>(out);
}

// round 7
// speedup vs baseline: 1.2569x; 1.0290x over previous
#include <cuda_runtime.h>
#include <math.h>

#define NTOT (8*64*256*256)

// ---------------- scratch ----------------
__device__ float  d_ARe[131072*64];
__device__ float  d_AIm[131072*64];
__device__ float2 d_Xf [512*128*64];
__device__ float2 d_Of [512*128*64];
__device__ float  d_Zre[131072*64];
__device__ float  d_Zim[131072*64];
__device__ float  d_T1RE[144*64];
__device__ float  d_T1IM[128*64];
__device__ float2 d_FHf [128*144];
__device__ float2 d_FHIf[256*80];
__device__ float  d_TC [64*128];
__device__ float  d_TS [64*128];
__device__ float2 d_wt [2*256*64*64];
__device__ float2 d_lbt[2*15*256*4*64];
__device__ float2 d_la [2*15*4*64];
__device__ float  d_gate[30];

__device__ __forceinline__ void cfma(float2& c, float2 a, float2 b) {
    c.x = fmaf(a.x, b.x, c.x); c.x = fmaf(-a.y, b.y, c.x);
    c.y = fmaf(a.x, b.y, c.y); c.y = fmaf( a.y, b.x, c.y);
}

// ---------------- tables ----------------
__global__ void init_tabs_k() {
    int id = blockIdx.x * 256 + threadIdx.x;
    const float S = 6.283185307179586f / 256.0f;
    if (id < 9216) {                        // T1RE [144][64]
        int s = id >> 6, ky = id & 63; float v = 0.f;
        if (s == 0) v = 1.f;
        else if (s == 1) v = (ky & 1) ? -1.f : 1.f;
        else if (s <= 128) v = cosf(S * (float)(((s - 1) * ky) & 255));
        d_T1RE[id] = v;
    } else if (id < 17408) {                // T1IM [128][64]
        int r = id - 9216, s = r >> 6, ky = r & 63; float v = 0.f;
        if (s <= 126) v = -sinf(S * (float)(((s + 1) * ky) & 255));
        d_T1IM[r] = v;
    } else if (id < 35840) {                // FHf [128][144]
        int r = id - 17408, m = r / 144, hp = r % 144;
        float2 v = make_float2(0.f, 0.f);
        if (hp <= 128) {
            int kx = (m < 64) ? m : m + 128;
            float a = S * (float)((kx * hp) & 255);
            v = make_float2(cosf(a), sinf(a));
        }
        d_FHf[r] = v;
    } else if (id < 56320) {                // FHIf [256][80]
        int r = id - 35840, h = r / 80, kk = r % 80;
        float2 v = make_float2(0.f, 0.f);
        if (kk <= 64) {
            int ke = (kk == 64) ? 192 : kk;
            float a = S * (float)((ke * h) & 255);
            v = make_float2(cosf(a), sinf(a));
        }
        d_FHIf[r] = v;
    } else if (id < 64512) {                // TC
        int r = id - 56320, ky = r >> 7, w = r & 127;
        float sc = ((ky == 0) ? 1.f : 2.f) * (1.f / 65536.f);
        d_TC[r] = sc * cosf(S * (float)((ky * w) & 255));
    } else if (id < 72704) {                // TS
        int r = id - 64512, ky = r >> 7, w = r & 127;
        float sc = ((ky == 0) ? 1.f : 2.f) * (1.f / 65536.f);
        d_TS[r] = sc * sinf(S * (float)((ky * w) & 255));
    }
}

__global__ void init_wt_k(const float* __restrict__ w1re, const float* __restrict__ w1im,
                          const float* __restrict__ w2re, const float* __restrict__ w2im) {
    int id = blockIdx.x * 256 + threadIdx.x;
    if (id >= 2 * 256 * 4096) return;
    int t = id >> 20, rem = id & 1048575;
    int p = rem >> 12, io = rem & 4095;
    int i = io >> 6, o = io & 63;
    const float* re = t ? w2re : w1re;
    const float* im = t ? w2im : w1im;
    size_t src = ((size_t)(i * 64 + o)) * 256 + p;
    d_wt[id] = make_float2(re[src], im[src]);
}

__global__ void init_lbt_k(const float* __restrict__ b1re, const float* __restrict__ b1im,
                           const float* __restrict__ b2re, const float* __restrict__ b2im) {
    int id = blockIdx.x * 256 + threadIdx.x;
    if (id >= 2 * 15 * 256 * 256) return;
    int t = id / 983040, rem = id % 983040;
    int e = rem >> 16, rem2 = rem & 65535;
    int p = rem2 >> 8, ro = rem2 & 255;
    int r = ro >> 6, o = ro & 63;
    const float* re = t ? b2re : b1re;
    const float* im = t ? b2im : b1im;
    size_t src = (((size_t)(e * 64 + o)) * 4 + r) * 256 + p;
    d_lbt[id] = make_float2(re[src], im[src]);
}

__global__ void init_small_k(const float* __restrict__ la1re, const float* __restrict__ la1im,
                             const float* __restrict__ la2re, const float* __restrict__ la2im,
                             const float* __restrict__ g1, const float* __restrict__ g2,
                             float* sp_out) {
    int tid = threadIdx.x;
    for (int id = tid; id < 7680; id += 256) {
        int t = id / 3840, rem = id % 3840;
        const float* re = t ? la2re : la1re;
        const float* im = t ? la2im : la1im;
        d_la[id] = make_float2(re[rem], im[rem]);
    }
    __shared__ float gs[30];
    if (tid < 30) {
        float v = (tid < 15) ? g1[tid] : g2[tid - 15];
        float s = 1.0f / (1.0f + expf(-v));
        d_gate[tid] = s; gs[tid] = s;
    }
    __syncthreads();
    if (tid == 0 && sp_out) {
        float s = 0.0f;
        for (int i = 0; i < 30; i++) s += gs[i];
        *sp_out = s / 15.0f;
    }
}

// ---------------- K1: fused fold + real GEMM (MODE 0: even/Re, 1: odd/Im) ----------------
template<int MODE>
__global__ __launch_bounds__(256) void k1gemm_k(const float* __restrict__ x) {
    const int Kdim = MODE ? 128 : 144;
    const float* T = MODE ? d_T1IM : d_T1RE;
    float* C = MODE ? d_AIm : d_ARe;
    __shared__ float As[16][128];
    __shared__ float Bs[16][64];
    int tid = threadIdx.x, m0 = blockIdx.x * 128;
    int tx = tid & 15, ty = tid >> 4;
    float acc[8][4] = {};
    for (int k0 = 0; k0 < Kdim; k0 += 16) {
#pragma unroll
        for (int l = 0; l < 2; l++) {
            int f = tid + l * 256, row = f >> 2, c4 = (f & 3) * 4;
            const float* xr = x + (size_t)(m0 + row) * 256;
#pragma unroll
            for (int j = 0; j < 4; j++) {
                int s = k0 + c4 + j; float v;
                if (MODE == 0) {
                    if (s == 0) v = xr[0];
                    else if (s == 1) v = xr[128];
                    else if (s <= 128) v = xr[s - 1] + xr[257 - s];
                    else v = 0.f;
                } else {
                    v = (s <= 126) ? (xr[s + 1] - xr[255 - s]) : 0.f;
                }
                As[c4 + j][row] = v;
            }
        }
        {
            int row = tid >> 4, c4 = (tid & 15) * 4;
            *(float4*)(&Bs[row][c4]) = *(const float4*)(T + (k0 + row) * 64 + c4);
        }
        __syncthreads();
#pragma unroll
        for (int k = 0; k < 16; k++) {
            float a[8], b[4];
#pragma unroll
            for (int i = 0; i < 4; i++) { a[i] = As[k][ty * 4 + i]; a[4 + i] = As[k][64 + ty * 4 + i]; }
#pragma unroll
            for (int j = 0; j < 4; j++) b[j] = Bs[k][tx * 4 + j];
#pragma unroll
            for (int i = 0; i < 8; i++)
#pragma unroll
                for (int j = 0; j < 4; j++)
                    acc[i][j] = fmaf(a[i], b[j], acc[i][j]);
        }
        __syncthreads();
    }
#pragma unroll
    for (int i = 0; i < 8; i++) {
        int m = m0 + ((i < 4) ? (ty * 4 + i) : (64 + ty * 4 + (i - 4)));
        float4 v = {acc[i][0], acc[i][1], acc[i][2], acc[i][3]};
        *(float4*)(C + (size_t)m * 64 + tx * 4) = v;
    }
}

// ---------------- fwd H-transform: fused h-fold + complex GEMM ----------------
// Xf[bat][m][ky] = sum_hp F[m][hp] ⊗ (S,D)   K=144, M=128
__global__ __launch_bounds__(256) void cgemm_fwd_k() {
    int bat = blockIdx.x, m0 = blockIdx.y * 64;
    const float* Rb = d_ARe + (size_t)bat * 16384;
    const float* Ib = d_AIm + (size_t)bat * 16384;
    __shared__ float2 Fs[16][64], Ss[16][64], Ds[16][64];
    int tid = threadIdx.x, tx = tid & 15, ty = tid >> 4;
    float2 acc[4][4] = {};
    for (int k0 = 0; k0 < 144; k0 += 16) {
#pragma unroll
        for (int l = 0; l < 2; l++) {
            int f = tid + l * 256, row = f >> 3, c = f & 7;
            float4 v = *(const float4*)(d_FHf + (size_t)(m0 + row) * 144 + k0 + 2 * c);
            Fs[2 * c][row]     = make_float2(v.x, v.y);
            Fs[2 * c + 1][row] = make_float2(v.z, v.w);
        }
        {
            int row = tid >> 4, ky0 = (tid & 15) * 4, hp = k0 + row;
            float4 sr = {0,0,0,0}, si = sr, dr = sr, di = sr;
            if (hp == 0 || hp == 128) {
                sr = *(const float4*)(Rb + hp * 64 + ky0);
                si = *(const float4*)(Ib + hp * 64 + ky0);
            } else if (hp < 128) {
                float4 pr = *(const float4*)(Rb + hp * 64 + ky0);
                float4 pi = *(const float4*)(Ib + hp * 64 + ky0);
                float4 qr = *(const float4*)(Rb + (256 - hp) * 64 + ky0);
                float4 qi = *(const float4*)(Ib + (256 - hp) * 64 + ky0);
                sr = make_float4(pr.x+qr.x, pr.y+qr.y, pr.z+qr.z, pr.w+qr.w);
                si = make_float4(pi.x+qi.x, pi.y+qi.y, pi.z+qi.z, pi.w+qi.w);
                dr = make_float4(pr.x-qr.x, pr.y-qr.y, pr.z-qr.z, pr.w-qr.w);
                di = make_float4(pi.x-qi.x, pi.y-qi.y, pi.z-qi.z, pi.w-qi.w);
            }
            Ss[row][ky0]   = make_float2(sr.x, si.x); Ss[row][ky0+1] = make_float2(sr.y, si.y);
            Ss[row][ky0+2] = make_float2(sr.z, si.z); Ss[row][ky0+3] = make_float2(sr.w, si.w);
            Ds[row][ky0]   = make_float2(dr.x, di.x); Ds[row][ky0+1] = make_float2(dr.y, di.y);
            Ds[row][ky0+2] = make_float2(dr.z, di.z); Ds[row][ky0+3] = make_float2(dr.w, di.w);
        }
        __syncthreads();
#pragma unroll
        for (int k = 0; k < 16; k++) {
            float2 fv[4], sv[4], dv[4];
#pragma unroll
            for (int i = 0; i < 4; i++) fv[i] = Fs[k][ty * 4 + i];
#pragma unroll
            for (int j = 0; j < 4; j++) { sv[j] = Ss[k][tx * 4 + j]; dv[j] = Ds[k][tx * 4 + j]; }
#pragma unroll
            for (int i = 0; i < 4; i++)
#pragma unroll
                for (int j = 0; j < 4; j++) {
                    acc[i][j].x = fmaf(sv[j].x, fv[i].x, acc[i][j].x);
                    acc[i][j].x = fmaf(dv[j].y, fv[i].y, acc[i][j].x);
                    acc[i][j].y = fmaf(sv[j].y, fv[i].x, acc[i][j].y);
                    acc[i][j].y = fmaf(-dv[j].x, fv[i].y, acc[i][j].y);
                }
        }
        __syncthreads();
    }
    float2* Cb = d_Xf + (size_t)bat * 8192;
#pragma unroll
    for (int i = 0; i < 4; i++) {
        int m = m0 + ty * 4 + i;
#pragma unroll
        for (int j = 0; j < 4; j += 2) {
            float4 v = {acc[i][j].x, acc[i][j].y, acc[i][j + 1].x, acc[i][j + 1].y};
            *(float4*)(Cb + (size_t)m * 64 + tx * 4 + j) = v;
        }
    }
}

// ---------------- spectral multiply ----------------
__global__ __launch_bounds__(512) void base_mul_k() {
    int t = blockIdx.x, p = blockIdx.y;
    int x = p >> 4, y = p & 15;
    int kxIdx = (t == 0) ? x : (112 + x);
    int ky = y;
    __shared__ float2 Xs[8][64];
    int tid = threadIdx.x;
    {
        int b = tid >> 6, i = tid & 63;
        Xs[b][i] = d_Xf[(size_t)(b * 64 + i) * 8192 + kxIdx * 64 + ky];
    }
    __syncthreads();
    int o = tid & 63, b = tid >> 6;
    const float2* wp = d_wt + ((size_t)t * 256 + p) * 4096;
    float2 s = {0.f, 0.f};
#pragma unroll 8
    for (int i = 0; i < 64; i++) cfma(s, Xs[b][i], wp[i * 64 + o]);
    d_Of[(size_t)(b * 64 + o) * 8192 + kxIdx * 64 + ky] = s;
}

__global__ __launch_bounds__(512) void expert_mul_k() {
    int tile = blockIdx.x;
    int half = tile / 15, e = tile % 15;
    int p = blockIdx.y;
    int x = p >> 4, y = p & 15;
    int Rr = (e + 1) >> 2, Cc = (e + 1) & 3;
    int ky = Cc * 16 + y;
    int kxIdx = (half == 0) ? (Rr * 16 + x) : (64 + (3 - Rr) * 16 + x);
    __shared__ float2 Xs[8][64];
    __shared__ float2 Ts[8][4];
    int tid = threadIdx.x;
    {
        int b = tid >> 6, i = tid & 63;
        Xs[b][i] = d_Xf[(size_t)(b * 64 + i) * 8192 + kxIdx * 64 + ky];
    }
    __syncthreads();
    if (tid < 32) {
        int b = tid >> 2, r = tid & 3;
        const float2* lap = d_la + (size_t)(half * 15 + e) * 256 + r * 64;
        float2 s = {0.f, 0.f};
#pragma unroll 8
        for (int i = 0; i < 64; i++) cfma(s, Xs[b][i], lap[i]);
        Ts[b][r] = s;
    }
    __syncthreads();
    int o = tid & 63, b = tid >> 6;
    const float2* lbp = d_lbt + ((size_t)(half * 15 + e) * 256 + p) * 256;
    float2 s = {0.f, 0.f};
#pragma unroll
    for (int r = 0; r < 4; r++) cfma(s, Ts[b][r], lbp[r * 64 + o]);
    float g = d_gate[half * 15 + e] * 0.1f;
    s.x *= g; s.y *= g;
    d_Of[(size_t)(b * 64 + o) * 8192 + kxIdx * 64 + ky] = s;
}

// ---------------- inv H-transform: fused kx-fold + complex GEMM, split output ----------------
// Z[bat][h][ky], K=80, M=256
__global__ __launch_bounds__(256) void cgemm_inv_k() {
    int bat = blockIdx.x, m0 = blockIdx.y * 64;
    const float2* Ob = d_Of + (size_t)bat * 8192;
    __shared__ float2 Fs[16][64], Ss[16][64], Ds[16][64];
    int tid = threadIdx.x, tx = tid & 15, ty = tid >> 4;
    float2 acc[4][4] = {};
    for (int k0 = 0; k0 < 80; k0 += 16) {
#pragma unroll
        for (int l = 0; l < 2; l++) {
            int f = tid + l * 256, row = f >> 3, c = f & 7;
            float4 v = *(const float4*)(d_FHIf + (size_t)(m0 + row) * 80 + k0 + 2 * c);
            Fs[2 * c][row]     = make_float2(v.x, v.y);
            Fs[2 * c + 1][row] = make_float2(v.z, v.w);
        }
#pragma unroll
        for (int l = 0; l < 2; l++) {
            int f = tid + l * 256, row = f >> 5, ky0 = (f & 31) * 2, kk = k0 + row;
            float4 S = {0,0,0,0}, D = S;
            if (kk == 0) {
                S = *(const float4*)(Ob + ky0);
            } else if (kk < 64) {
                float4 p = *(const float4*)(Ob + kk * 64 + ky0);
                float4 q = *(const float4*)(Ob + (128 - kk) * 64 + ky0);
                S = make_float4(p.x+q.x, p.y+q.y, p.z+q.z, p.w+q.w);
                D = make_float4(p.x-q.x, p.y-q.y, p.z-q.z, p.w-q.w);
            } else if (kk == 64) {
                S = *(const float4*)(Ob + 64 * 64 + ky0);
                D = S;
            }
            Ss[row][ky0] = make_float2(S.x, S.y); Ss[row][ky0 + 1] = make_float2(S.z, S.w);
            Ds[row][ky0] = make_float2(D.x, D.y); Ds[row][ky0 + 1] = make_float2(D.z, D.w);
        }
        __syncthreads();
#pragma unroll
        for (int k = 0; k < 16; k++) {
            float2 fv[4], sv[4], dv[4];
#pragma unroll
            for (int i = 0; i < 4; i++) fv[i] = Fs[k][ty * 4 + i];
#pragma unroll
            for (int j = 0; j < 4; j++) { sv[j] = Ss[k][tx * 4 + j]; dv[j] = Ds[k][tx * 4 + j]; }
#pragma unroll
            for (int i = 0; i < 4; i++)
#pragma unroll
                for (int j = 0; j < 4; j++) {
                    acc[i][j].x = fmaf(sv[j].x, fv[i].x, acc[i][j].x);
                    acc[i][j].x = fmaf(-dv[j].y, fv[i].y, acc[i][j].x);
                    acc[i][j].y = fmaf(sv[j].y, fv[i].x, acc[i][j].y);
                    acc[i][j].y = fmaf(dv[j].x, fv[i].y, acc[i][j].y);
                }
        }
        __syncthreads();
    }
    float* Rb = d_Zre + (size_t)bat * 16384;
    float* Ib = d_Zim + (size_t)bat * 16384;
#pragma unroll
    for (int i = 0; i < 4; i++) {
        int m = m0 + ty * 4 + i;
        float4 vr = {acc[i][0].x, acc[i][1].x, acc[i][2].x, acc[i][3].x};
        float4 vi = {acc[i][0].y, acc[i][1].y, acc[i][2].y, acc[i][3].y};
        *(float4*)(Rb + (size_t)m * 64 + tx * 4) = vr;
        *(float4*)(Ib + (size_t)m * 64 + tx * 4) = vi;
    }
}

// ---------------- K6: fused irfft-W with w-fold ----------------
__global__ __launch_bounds__(256) void k6_k(float* __restrict__ out) {
    __shared__ float Rs[16][128], Is[16][128], Cs[16][64], Sn[16][64];
    int tid = threadIdx.x, m0 = blockIdx.x * 128, n0 = blockIdx.y * 64;
    int tx = tid & 15, ty = tid >> 4;
    float accP[8][4] = {}, accQ[8][4] = {};
    for (int k0 = 0; k0 < 64; k0 += 16) {
#pragma unroll
        for (int l = 0; l < 2; l++) {
            int f = tid + l * 256, row = f >> 2, c4 = (f & 3) * 4;
            float4 v = *(const float4*)(d_Zre + (size_t)(m0 + row) * 64 + k0 + c4);
            Rs[c4][row] = v.x; Rs[c4 + 1][row] = v.y; Rs[c4 + 2][row] = v.z; Rs[c4 + 3][row] = v.w;
            float4 u = *(const float4*)(d_Zim + (size_t)(m0 + row) * 64 + k0 + c4);
            Is[c4][row] = u.x; Is[c4 + 1][row] = u.y; Is[c4 + 2][row] = u.z; Is[c4 + 3][row] = u.w;
        }
        {
            int row = tid >> 4, c4 = (tid & 15) * 4;
            *(float4*)(&Cs[row][c4]) = *(const float4*)(d_TC + (k0 + row) * 128 + n0 + c4);
            *(float4*)(&Sn[row][c4]) = *(const float4*)(d_TS + (k0 + row) * 128 + n0 + c4);
        }
        __syncthreads();
#pragma unroll
        for (int k = 0; k < 16; k++) {
            float ar[8], ai[8], bc[4], bs[4];
#pragma unroll
            for (int i = 0; i < 4; i++) {
                ar[i] = Rs[k][ty * 4 + i]; ar[4 + i] = Rs[k][64 + ty * 4 + i];
                ai[i] = Is[k][ty * 4 + i]; ai[4 + i] = Is[k][64 + ty * 4 + i];
            }
#pragma unroll
            for (int j = 0; j < 4; j++) { bc[j] = Cs[k][tx * 4 + j]; bs[j] = Sn[k][tx * 4 + j]; }
#pragma unroll
            for (int i = 0; i < 8; i++)
#pragma unroll
                for (int j = 0; j < 4; j++) {
                    accP[i][j] = fmaf(ar[i], bc[j], accP[i][j]);
                    accQ[i][j] = fmaf(ai[i], bs[j], accQ[i][j]);
                }
        }
        __syncthreads();
    }
#pragma unroll
    for (int i = 0; i < 8; i++) {
        int m = m0 + ((i < 4) ? (ty * 4 + i) : (64 + ty * 4 + (i - 4)));
        int w = n0 + tx * 4;
        float4 v = {accP[i][0] - accQ[i][0], accP[i][1] - accQ[i][1],
                    accP[i][2] - accQ[i][2], accP[i][3] - accQ[i][3]};
        *(float4*)(out + (size_t)m * 256 + w) = v;
#pragma unroll
        for (int j = 0; j < 4; j++) {
            int wj = w + j;
            if (wj > 0) out[(size_t)m * 256 + 256 - wj] = accP[i][j] + accQ[i][j];
        }
    }
}

__global__ void y128_k(float* __restrict__ out) {
    int m = blockIdx.x * 256 + threadIdx.x;
    const float* z = d_Zre + (size_t)m * 64;
    float s = z[0] * (1.f / 65536.f);
#pragma unroll 8
    for (int k = 1; k < 64; k++)
        s = fmaf(z[k], ((k & 1) ? -2.f : 2.f) * (1.f / 65536.f), s);
    out[(size_t)m * 256 + 128] = s;
}

// ---------------------------------- launch ----------------------------------
extern "C" void kernel_launch(void* const* d_in, const int* in_sizes, int n_in,
                              void* d_out, int out_size) {
    const float* x     = (const float*)d_in[0];
    const float* w1re  = (const float*)d_in[1];
    const float* w1im  = (const float*)d_in[2];
    const float* w2re  = (const float*)d_in[3];
    const float* w2im  = (const float*)d_in[4];
    const float* la1re = (const float*)d_in[5];
    const float* la1im = (const float*)d_in[6];
    const float* lb1re = (const float*)d_in[7];
    const float* lb1im = (const float*)d_in[8];
    const float* la2re = (const float*)d_in[9];
    const float* la2im = (const float*)d_in[10];
    const float* lb2re = (const float*)d_in[11];
    const float* lb2im = (const float*)d_in[12];
    const float* g1    = (const float*)d_in[13];
    const float* g2    = (const float*)d_in[14];
    float* out = (float*)d_out;

    float* sp_out = (out_size > NTOT) ? (out + NTOT) : nullptr;

    init_tabs_k<<<288, 256>>>();
    init_wt_k<<<8192, 256>>>(w1re, w1im, w2re, w2im);
    init_lbt_k<<<7680, 256>>>(lb1re, lb1im, lb2re, lb2im);
    init_small_k<<<1, 256>>>(la1re, la1im, la2re, la2im, g1, g2, sp_out);

    k1gemm_k<0><<<1024, 256>>>(x);
    k1gemm_k<1><<<1024, 256>>>(x);
    cgemm_fwd_k<<<dim3(512, 2), 256>>>();
    base_mul_k<<<dim3(2, 256), 512>>>();
    expert_mul_k<<<dim3(30, 256), 512>>>();
    cgemm_inv_k<<<dim3(512, 4), 256>>>();
    k6_k<<<dim3(1024, 2), 256>>>(out);
    y128_k<<<512, 256>>>(out);
}

// round 10
// speedup vs baseline: 1.7144x; 1.3640x over previous
#include <cuda_runtime.h>
#include <cuda_bf16.h>
#include <math.h>
#include <stdint.h>

#define NTOT (8*64*256*256)

// ---------------- scratch ----------------
__device__ float  d_Bp [512*512*128];   // K1 out, duplicated complex rows [bc][2h+d][2ky+c] (134 MB)
__device__ float2 d_Xf [512*128*64];    // x_ft corners [bc][kx][ky]                        (33 MB)
__device__ float  d_Ofd[512*256*128];   // spectral out, duplicated [bo][2kx+d][2ky+c]      (67 MB)
__device__ float  d_Z  [512*256*128];   // inv-H out [bo][h][2ky+c]                          (67 MB)
// bf16-split twiddle tables
__device__ __nv_bfloat16 d_FW2hi [256*128], d_FW2lo [256*128];
__device__ __nv_bfloat16 d_FH2hi [128*512], d_FH2lo [128*512];
__device__ __nv_bfloat16 d_FHI2hi[256*256], d_FHI2lo[256*256];
__device__ __nv_bfloat16 d_FIW2hi[128*256], d_FIW2lo[128*256];
// spectral weights
__device__ float2 d_wt [2*256*64*64];
__device__ float2 d_lbt[2*15*256*4*64];
__device__ float2 d_la [2*15*4*64];
__device__ float  d_gate[30];

__device__ __forceinline__ void cfma(float2& c, float2 a, float2 b) {
    c.x = fmaf(a.x, b.x, c.x); c.x = fmaf(-a.y, b.y, c.x);
    c.y = fmaf(a.x, b.y, c.y); c.y = fmaf( a.y, b.x, c.y);
}

__device__ __forceinline__ void split2(float a, float b, __nv_bfloat162& h, __nv_bfloat162& l) {
    __nv_bfloat16 ha = __float2bfloat16(a), hb = __float2bfloat16(b);
    h.x = ha; h.y = hb;
    l.x = __float2bfloat16(a - __bfloat162float(ha));
    l.y = __float2bfloat16(b - __bfloat162float(hb));
}

__device__ __forceinline__ void ldsm4(uint32_t addr, uint32_t& r0, uint32_t& r1, uint32_t& r2, uint32_t& r3) {
    asm volatile("ldmatrix.sync.aligned.m8n8.x4.shared.b16 {%0,%1,%2,%3}, [%4];"
                 : "=r"(r0), "=r"(r1), "=r"(r2), "=r"(r3) : "r"(addr));
}
__device__ __forceinline__ void ldsm4t(uint32_t addr, uint32_t& r0, uint32_t& r1, uint32_t& r2, uint32_t& r3) {
    asm volatile("ldmatrix.sync.aligned.m8n8.x4.trans.shared.b16 {%0,%1,%2,%3}, [%4];"
                 : "=r"(r0), "=r"(r1), "=r"(r2), "=r"(r3) : "r"(addr));
}
__device__ __forceinline__ void mma16816(float* c, const uint32_t* a, const uint32_t* b) {
    asm volatile("mma.sync.aligned.m16n8k16.row.col.f32.bf16.bf16.f32 "
                 "{%0,%1,%2,%3},{%4,%5,%6,%7},{%8,%9},{%0,%1,%2,%3};"
                 : "+f"(c[0]), "+f"(c[1]), "+f"(c[2]), "+f"(c[3])
                 : "r"(a[0]), "r"(a[1]), "r"(a[2]), "r"(a[3]), "r"(b[0]), "r"(b[1]));
}

// ---------------- table init (fp32 value -> bf16 hi/lo split) ----------------
__global__ void init_tabs2_k() {
    int id = blockIdx.x * 256 + threadIdx.x;   // 196608 total
    const float S = 6.283185307179586f / 256.0f;
    float v; __nv_bfloat16 *hi, *lo; int idx;
    if (id < 32768) {                          // FW2 [w][2ky+c] (rfft W)
        int w = id >> 7, n = id & 127, ky = n >> 1;
        float a = S * (float)((w * ky) & 255);
        v = (n & 1) ? -sinf(a) : cosf(a);
        hi = d_FW2hi; lo = d_FW2lo; idx = id;
    } else if (id < 98304) {                   // FH2 [kxIdx][2h+d] (fwd H, e^{-i})
        int r = id - 32768; int m = r >> 9, q = r & 511;
        int h = q >> 1, dd = q & 1;
        int kx = (m < 64) ? m : m + 128;
        float a = S * (float)((kx * h) & 255);
        v = dd ? -sinf(a) : cosf(a);
        hi = d_FH2hi; lo = d_FH2lo; idx = r;
    } else if (id < 163840) {                  // FHI2 [h][2kxIdx+d] (inv H, e^{+i})
        int r = id - 98304; int h = r >> 8, q = r & 255;
        int kxi = q >> 1, dd = q & 1;
        int kx = (kxi < 64) ? kxi : kxi + 128;
        float a = S * (float)((kx * h) & 255);
        v = dd ? sinf(a) : cosf(a);
        hi = d_FHI2hi; lo = d_FHI2lo; idx = r;
    } else {                                   // FIW2 [2ky+c][w] (irfft W, scaled)
        int r = id - 163840; int n = r >> 8, w = r & 255; int ky = n >> 1;
        float s = ((ky == 0) ? 1.f : 2.f) * (1.f / 65536.f);
        float a = S * (float)((ky * w) & 255);
        v = (n & 1) ? -s * sinf(a) : s * cosf(a);
        hi = d_FIW2hi; lo = d_FIW2lo; idx = r;
    }
    __nv_bfloat16 h16 = __float2bfloat16(v);
    hi[idx] = h16;
    lo[idx] = __float2bfloat16(v - __bfloat162float(h16));
}

__global__ void init_wt_k(const float* __restrict__ w1re, const float* __restrict__ w1im,
                          const float* __restrict__ w2re, const float* __restrict__ w2im) {
    int id = blockIdx.x * 256 + threadIdx.x;
    if (id >= 2 * 256 * 4096) return;
    int t = id >> 20, rem = id & 1048575;
    int p = rem >> 12, io = rem & 4095;
    int i = io >> 6, o = io & 63;
    const float* re = t ? w2re : w1re;
    const float* im = t ? w2im : w1im;
    size_t src = ((size_t)(i * 64 + o)) * 256 + p;
    d_wt[id] = make_float2(re[src], im[src]);
}

__global__ void init_lbt_k(const float* __restrict__ b1re, const float* __restrict__ b1im,
                           const float* __restrict__ b2re, const float* __restrict__ b2im) {
    int id = blockIdx.x * 256 + threadIdx.x;
    if (id >= 2 * 15 * 256 * 256) return;
    int t = id / 983040, rem = id % 983040;
    int e = rem >> 16, rem2 = rem & 65535;
    int p = rem2 >> 8, ro = rem2 & 255;
    int r = ro >> 6, o = ro & 63;
    const float* re = t ? b2re : b1re;
    const float* im = t ? b2im : b1im;
    size_t src = (((size_t)(e * 64 + o)) * 4 + r) * 256 + p;
    d_lbt[id] = make_float2(re[src], im[src]);
}

__global__ void init_small_k(const float* __restrict__ la1re, const float* __restrict__ la1im,
                             const float* __restrict__ la2re, const float* __restrict__ la2im,
                             const float* __restrict__ g1, const float* __restrict__ g2,
                             float* sp_out) {
    int tid = threadIdx.x;
    for (int id = tid; id < 7680; id += 256) {
        int t = id / 3840, rem = id % 3840;
        const float* re = t ? la2re : la1re;
        const float* im = t ? la2im : la1im;
        d_la[id] = make_float2(re[rem], im[rem]);
    }
    __shared__ float gs[30];
    if (tid < 30) {
        float v = (tid < 15) ? g1[tid] : g2[tid - 15];
        float s = 1.0f / (1.0f + expf(-v));
        d_gate[tid] = s; gs[tid] = s;
    }
    __syncthreads();
    if (tid == 0 && sp_out) {
        float s = 0.0f;
        for (int i = 0; i < 30; i++) s += gs[i];
        *sp_out = s / 15.0f;
    }
}

// ---------------- unified bf16-split tensor-core GEMM ----------------
// BM=128, BN=64, BK=32, 256 threads (8 warps, 4x2), warp tile 32x32.
// STAGE 0: C=x*FW2 -> d_Bp (duplicated rows)     M=131072 K=256
// STAGE 1: C=FH2*Bp[bc] -> d_Xf                  M=128    K=512
// STAGE 2: C=FHI2*Ofd[bo] -> d_Z                 M=256    K=256
// STAGE 3: C=Z*FIW2 -> out                       M=131072 K=128
template<int STAGE, int KDIM, int LDB>
__global__ __launch_bounds__(256) void mma_gemm_k(const float* __restrict__ xin,
                                                  float* __restrict__ yout) {
    constexpr bool AFP32 = (STAGE == 0 || STAGE == 3);
    __shared__ __align__(16) __nv_bfloat16 Ah[128*40], Al[128*40], Bh[32*72], Bl[32*72];
    int tid = threadIdx.x, lane = tid & 31, warp = tid >> 5;
    int wy = warp >> 1, wx = warp & 1;
    int mw = wy * 32, nw = wx * 32;
    int g = lane >> 3, lr = lane & 7;
    int f_row = (g & 1) * 8 + lr;   // ldmatrix lane row
    int f_col = (g >> 1) * 8;       // ldmatrix lane col group

    int m0 = 0, n0 = 0, bat = 0;
    if constexpr (STAGE == 0) { m0 = blockIdx.x * 128; n0 = blockIdx.y * 64; }
    if constexpr (STAGE == 1) { bat = blockIdx.x; n0 = blockIdx.y * 64; }
    if constexpr (STAGE == 2) { bat = blockIdx.x; m0 = (blockIdx.y >> 1) * 128; n0 = (blockIdx.y & 1) * 64; }
    if constexpr (STAGE == 3) { m0 = blockIdx.x * 128; n0 = blockIdx.y * 64; }

    const float* Afp = nullptr;
    const __nv_bfloat16 *Ahg = nullptr, *Alg = nullptr, *Bhg = nullptr, *Blg = nullptr;
    const float* Bfp = nullptr;
    if constexpr (STAGE == 0) { Afp = xin;  Bhg = d_FW2hi;  Blg = d_FW2lo; }
    if constexpr (STAGE == 1) { Ahg = d_FH2hi;  Alg = d_FH2lo;  Bfp = d_Bp  + (size_t)bat * 65536; }
    if constexpr (STAGE == 2) { Ahg = d_FHI2hi; Alg = d_FHI2lo; Bfp = d_Ofd + (size_t)bat * 32768; }
    if constexpr (STAGE == 3) { Afp = d_Z;  Bhg = d_FIW2hi; Blg = d_FIW2lo; }

    float c[2][4][4] = {};
    uint32_t sAh = (uint32_t)__cvta_generic_to_shared(Ah);
    uint32_t sAl = (uint32_t)__cvta_generic_to_shared(Al);
    uint32_t sBh = (uint32_t)__cvta_generic_to_shared(Bh);
    uint32_t sBl = (uint32_t)__cvta_generic_to_shared(Bl);

#pragma unroll 2
    for (int k0 = 0; k0 < KDIM; k0 += 32) {
        {   // A tile [128][32]
            int row = tid >> 1, cb = (tid & 1) * 16;
            if constexpr (AFP32) {
                const float* ap = Afp + (size_t)(m0 + row) * KDIM + k0 + cb;
#pragma unroll
                for (int i = 0; i < 4; i++) {
                    float4 v = ((const float4*)ap)[i];
                    __nv_bfloat162 h0, l0, h1, l1;
                    split2(v.x, v.y, h0, l0); split2(v.z, v.w, h1, l1);
                    int o = row * 40 + cb + i * 4;
                    *(__nv_bfloat162*)&Ah[o]     = h0; *(__nv_bfloat162*)&Ah[o + 2] = h1;
                    *(__nv_bfloat162*)&Al[o]     = l0; *(__nv_bfloat162*)&Al[o + 2] = l1;
                }
            } else {
                size_t src = (size_t)(m0 + row) * KDIM + k0 + cb;
                *(uint4*)&Ah[row * 40 + cb]     = ((const uint4*)(Ahg + src))[0];
                *(uint4*)&Ah[row * 40 + cb + 8] = ((const uint4*)(Ahg + src))[1];
                *(uint4*)&Al[row * 40 + cb]     = ((const uint4*)(Alg + src))[0];
                *(uint4*)&Al[row * 40 + cb + 8] = ((const uint4*)(Alg + src))[1];
            }
        }
        {   // B tile [32][64]
            int row = tid >> 3, cb = (tid & 7) * 8;
            if constexpr (AFP32) {   // B static bf16
                size_t src = (size_t)(k0 + row) * LDB + n0 + cb;
                *(uint4*)&Bh[row * 72 + cb] = *(const uint4*)(Bhg + src);
                *(uint4*)&Bl[row * 72 + cb] = *(const uint4*)(Blg + src);
            } else {                 // B fp32 -> split
                const float* bp = Bfp + (size_t)(k0 + row) * LDB + n0 + cb;
                float4 v0 = ((const float4*)bp)[0], v1 = ((const float4*)bp)[1];
                __nv_bfloat162 h0, l0, h1, l1, h2, l2, h3, l3;
                split2(v0.x, v0.y, h0, l0); split2(v0.z, v0.w, h1, l1);
                split2(v1.x, v1.y, h2, l2); split2(v1.z, v1.w, h3, l3);
                int o = row * 72 + cb;
                *(__nv_bfloat162*)&Bh[o]     = h0; *(__nv_bfloat162*)&Bh[o + 2] = h1;
                *(__nv_bfloat162*)&Bh[o + 4] = h2; *(__nv_bfloat162*)&Bh[o + 6] = h3;
                *(__nv_bfloat162*)&Bl[o]     = l0; *(__nv_bfloat162*)&Bl[o + 2] = l1;
                *(__nv_bfloat162*)&Bl[o + 4] = l2; *(__nv_bfloat162*)&Bl[o + 6] = l3;
            }
        }
        __syncthreads();
#pragma unroll
        for (int ks = 0; ks < 2; ks++) {
            int koff = ks * 16;
            uint32_t ah[2][4], al[2][4];
#pragma unroll
            for (int mi = 0; mi < 2; mi++) {
                uint32_t off = (uint32_t)(((mw + mi * 16 + f_row) * 40 + koff + f_col) * 2);
                ldsm4(sAh + off, ah[mi][0], ah[mi][1], ah[mi][2], ah[mi][3]);
                ldsm4(sAl + off, al[mi][0], al[mi][1], al[mi][2], al[mi][3]);
            }
            uint32_t bh[4][2], bl[4][2];
#pragma unroll
            for (int p = 0; p < 2; p++) {
                uint32_t off = (uint32_t)(((koff + f_row) * 72 + nw + p * 16 + f_col) * 2);
                uint32_t r0, r1, r2, r3;
                ldsm4t(sBh + off, r0, r1, r2, r3);
                bh[2*p][0] = r0; bh[2*p][1] = r1; bh[2*p+1][0] = r2; bh[2*p+1][1] = r3;
                ldsm4t(sBl + off, r0, r1, r2, r3);
                bl[2*p][0] = r0; bl[2*p][1] = r1; bl[2*p+1][0] = r2; bl[2*p+1][1] = r3;
            }
#pragma unroll
            for (int mi = 0; mi < 2; mi++)
#pragma unroll
                for (int ni = 0; ni < 4; ni++) {
                    mma16816(c[mi][ni], ah[mi], bh[ni]);
                    mma16816(c[mi][ni], ah[mi], bl[ni]);
                    mma16816(c[mi][ni], al[mi], bh[ni]);
                }
        }
        __syncthreads();
    }
    // epilogue
#pragma unroll
    for (int mi = 0; mi < 2; mi++)
#pragma unroll
        for (int ni = 0; ni < 4; ni++) {
            int gm = m0 + mw + mi * 16 + (lane >> 2);
            int gn = n0 + nw + ni * 8 + (lane & 3) * 2;
            float v0 = c[mi][ni][0], v1 = c[mi][ni][1];
            float v2 = c[mi][ni][2], v3 = c[mi][ni][3];
            if constexpr (STAGE == 0) {
                int bc = gm >> 8, h = gm & 255;
                float2* Bp2 = (float2*)d_Bp + (size_t)bc * 32768;
                Bp2[(2 * h)     * 64 + (gn >> 1)] = make_float2(v0, v1);
                Bp2[(2 * h + 1) * 64 + (gn >> 1)] = make_float2(-v1, v0);
                int h2 = h + 8;
                Bp2[(2 * h2)     * 64 + (gn >> 1)] = make_float2(v2, v3);
                Bp2[(2 * h2 + 1) * 64 + (gn >> 1)] = make_float2(-v3, v2);
            } else if constexpr (STAGE == 1) {
                float2* C2 = d_Xf + (size_t)bat * 8192;
                C2[gm * 64 + (gn >> 1)]       = make_float2(v0, v1);
                C2[(gm + 8) * 64 + (gn >> 1)] = make_float2(v2, v3);
            } else if constexpr (STAGE == 2) {
                float2* C2 = (float2*)d_Z + (size_t)bat * 16384;
                C2[gm * 64 + (gn >> 1)]       = make_float2(v0, v1);
                C2[(gm + 8) * 64 + (gn >> 1)] = make_float2(v2, v3);
            } else {
                float2* C2 = (float2*)yout;
                C2[(size_t)gm * 128 + (gn >> 1)]       = make_float2(v0, v1);
                C2[(size_t)(gm + 8) * 128 + (gn >> 1)] = make_float2(v2, v3);
            }
        }
}

// ---------------- spectral multiply (fp32; writes duplicated Ofd) ----------------
__global__ __launch_bounds__(512) void base_mul_k() {
    int t = blockIdx.x, p = blockIdx.y;
    int x = p >> 4, y = p & 15;
    int kxIdx = (t == 0) ? x : (112 + x);
    int ky = y;
    __shared__ float2 Xs[8][64];
    int tid = threadIdx.x;
    {
        int b = tid >> 6, i = tid & 63;
        Xs[b][i] = d_Xf[(size_t)(b * 64 + i) * 8192 + kxIdx * 64 + ky];
    }
    __syncthreads();
    int o = tid & 63, b = tid >> 6;
    const float2* wp = d_wt + ((size_t)t * 256 + p) * 4096;
    float2 s = {0.f, 0.f};
#pragma unroll 8
    for (int i = 0; i < 64; i++) cfma(s, Xs[b][i], wp[i * 64 + o]);
    float2* Od = (float2*)d_Ofd + (size_t)(b * 64 + o) * 16384;
    Od[(2 * kxIdx)     * 64 + ky] = s;
    Od[(2 * kxIdx + 1) * 64 + ky] = make_float2(-s.y, s.x);
}

__global__ __launch_bounds__(512) void expert_mul_k() {
    int tile = blockIdx.x;
    int half = tile / 15, e = tile % 15;
    int p = blockIdx.y;
    int x = p >> 4, y = p & 15;
    int Rr = (e + 1) >> 2, Cc = (e + 1) & 3;
    int ky = Cc * 16 + y;
    int kxIdx = (half == 0) ? (Rr * 16 + x) : (64 + (3 - Rr) * 16 + x);
    __shared__ float2 Xs[8][64];
    __shared__ float2 Ts[8][4];
    int tid = threadIdx.x;
    {
        int b = tid >> 6, i = tid & 63;
        Xs[b][i] = d_Xf[(size_t)(b * 64 + i) * 8192 + kxIdx * 64 + ky];
    }
    __syncthreads();
    if (tid < 32) {
        int b = tid >> 2, r = tid & 3;
        const float2* lap = d_la + (size_t)(half * 15 + e) * 256 + r * 64;
        float2 s = {0.f, 0.f};
#pragma unroll 8
        for (int i = 0; i < 64; i++) cfma(s, Xs[b][i], lap[i]);
        Ts[b][r] = s;
    }
    __syncthreads();
    int o = tid & 63, b = tid >> 6;
    const float2* lbp = d_lbt + ((size_t)(half * 15 + e) * 256 + p) * 256;
    float2 s = {0.f, 0.f};
#pragma unroll
    for (int r = 0; r < 4; r++) cfma(s, Ts[b][r], lbp[r * 64 + o]);
    float gsc = d_gate[half * 15 + e] * 0.1f;
    s.x *= gsc; s.y *= gsc;
    float2* Od = (float2*)d_Ofd + (size_t)(b * 64 + o) * 16384;
    Od[(2 * kxIdx)     * 64 + ky] = s;
    Od[(2 * kxIdx + 1) * 64 + ky] = make_float2(-s.y, s.x);
}

// ---------------------------------- launch ----------------------------------
extern "C" void kernel_launch(void* const* d_in, const int* in_sizes, int n_in,
                              void* d_out, int out_size) {
    const float* x     = (const float*)d_in[0];
    const float* w1re  = (const float*)d_in[1];
    const float* w1im  = (const float*)d_in[2];
    const float* w2re  = (const float*)d_in[3];
    const float* w2im  = (const float*)d_in[4];
    const float* la1re = (const float*)d_in[5];
    const float* la1im = (const float*)d_in[6];
    const float* lb1re = (const float*)d_in[7];
    const float* lb1im = (const float*)d_in[8];
    const float* la2re = (const float*)d_in[9];
    const float* la2im = (const float*)d_in[10];
    const float* lb2re = (const float*)d_in[11];
    const float* lb2im = (const float*)d_in[12];
    const float* g1    = (const float*)d_in[13];
    const float* g2    = (const float*)d_in[14];
    float* out = (float*)d_out;

    float* sp_out = (out_size > NTOT) ? (out + NTOT) : nullptr;

    init_tabs2_k<<<768, 256>>>();
    init_wt_k<<<8192, 256>>>(w1re, w1im, w2re, w2im);
    init_lbt_k<<<7680, 256>>>(lb1re, lb1im, lb2re, lb2im);
    init_small_k<<<1, 256>>>(la1re, la1im, la2re, la2im, g1, g2, sp_out);

    // K1: rfft along W -> duplicated B'            (M=131072, K=256, N=128)
    mma_gemm_k<0, 256, 128><<<dim3(1024, 2), 256>>>(x, nullptr);
    // K2: fwd H (real-ified complex GEMM)          (per-batch M=128, K=512, N=128)
    mma_gemm_k<1, 512, 128><<<dim3(512, 2), 256>>>(nullptr, nullptr);
    // spectral multiply (fp32)
    base_mul_k<<<dim3(2, 256), 512>>>();
    expert_mul_k<<<dim3(30, 256), 512>>>();
    // K5: inv H                                     (per-batch M=256, K=256, N=128)
    mma_gemm_k<2, 256, 128><<<dim3(512, 4), 256>>>(nullptr, nullptr);
    // K6: irfft along W -> out                      (M=131072, K=128, N=256)
    mma_gemm_k<3, 128, 256><<<dim3(1024, 4), 256>>>(nullptr, out);
}

// round 11
// speedup vs baseline: 1.7772x; 1.0366x over previous
#include <cuda_runtime.h>
#include <cuda_bf16.h>
#include <math.h>
#include <stdint.h>

#define NTOT (8*64*256*256)

// ---------------- scratch ----------------
// all big intermediates stored as bf16 hi/lo splits
__device__ __nv_bfloat16 d_BpH[512*256*128], d_BpL[512*256*128];  // K1 out [bc][h][2ky+c]
__device__ float2        d_Xf [512*128*64];                       // x_ft corners [bc][kx][ky]
__device__ __nv_bfloat16 d_OfH[512*128*128], d_OfL[512*128*128];  // spectral out [bo][kx][2ky+c]
__device__ __nv_bfloat16 d_ZH [512*256*128], d_ZL [512*256*128];  // inv-H out [bo][h][2ky+c]
// bf16-split twiddle tables
__device__ __nv_bfloat16 d_FW2hi [256*128], d_FW2lo [256*128];
__device__ __nv_bfloat16 d_FH2hi [128*512], d_FH2lo [128*512];
__device__ __nv_bfloat16 d_FHI2hi[256*256], d_FHI2lo[256*256];
__device__ __nv_bfloat16 d_FIW2hi[128*256], d_FIW2lo[128*256];
// spectral weights
__device__ float2 d_wt [2*256*64*64];
__device__ float2 d_lbt[2*15*256*4*64];
__device__ float2 d_la [2*15*4*64];
__device__ float  d_gate[30];

__device__ __forceinline__ void cfma(float2& c, float2 a, float2 b) {
    c.x = fmaf(a.x, b.x, c.x); c.x = fmaf(-a.y, b.y, c.x);
    c.y = fmaf(a.x, b.y, c.y); c.y = fmaf( a.y, b.x, c.y);
}

__device__ __forceinline__ void split2(float a, float b, __nv_bfloat162& h, __nv_bfloat162& l) {
    __nv_bfloat16 ha = __float2bfloat16(a), hb = __float2bfloat16(b);
    h.x = ha; h.y = hb;
    l.x = __float2bfloat16(a - __bfloat162float(ha));
    l.y = __float2bfloat16(b - __bfloat162float(hb));
}

__device__ __forceinline__ void store_split2(__nv_bfloat16* H, __nv_bfloat16* L,
                                             size_t idx, float a, float b) {
    __nv_bfloat162 h, l; split2(a, b, h, l);
    *(__nv_bfloat162*)(H + idx) = h;
    *(__nv_bfloat162*)(L + idx) = l;
}

__device__ __forceinline__ void ldsm4(uint32_t addr, uint32_t& r0, uint32_t& r1, uint32_t& r2, uint32_t& r3) {
    asm volatile("ldmatrix.sync.aligned.m8n8.x4.shared.b16 {%0,%1,%2,%3}, [%4];"
                 : "=r"(r0), "=r"(r1), "=r"(r2), "=r"(r3) : "r"(addr));
}
__device__ __forceinline__ void ldsm4t(uint32_t addr, uint32_t& r0, uint32_t& r1, uint32_t& r2, uint32_t& r3) {
    asm volatile("ldmatrix.sync.aligned.m8n8.x4.trans.shared.b16 {%0,%1,%2,%3}, [%4];"
                 : "=r"(r0), "=r"(r1), "=r"(r2), "=r"(r3) : "r"(addr));
}
__device__ __forceinline__ void mma16816(float* c, const uint32_t* a, const uint32_t* b) {
    asm volatile("mma.sync.aligned.m16n8k16.row.col.f32.bf16.bf16.f32 "
                 "{%0,%1,%2,%3},{%4,%5,%6,%7},{%8,%9},{%0,%1,%2,%3};"
                 : "+f"(c[0]), "+f"(c[1]), "+f"(c[2]), "+f"(c[3])
                 : "r"(a[0]), "r"(a[1]), "r"(a[2]), "r"(a[3]), "r"(b[0]), "r"(b[1]));
}

// ---------------- table init ----------------
__global__ void init_tabs2_k() {
    int id = blockIdx.x * 256 + threadIdx.x;   // 196608 total
    const float S = 6.283185307179586f / 256.0f;
    float v; __nv_bfloat16 *hi, *lo; int idx;
    if (id < 32768) {                          // FW2 [w][2ky+c]
        int w = id >> 7, n = id & 127, ky = n >> 1;
        float a = S * (float)((w * ky) & 255);
        v = (n & 1) ? -sinf(a) : cosf(a);
        hi = d_FW2hi; lo = d_FW2lo; idx = id;
    } else if (id < 98304) {                   // FH2 [kxIdx][2h+d]
        int r = id - 32768; int m = r >> 9, q = r & 511;
        int h = q >> 1, dd = q & 1;
        int kx = (m < 64) ? m : m + 128;
        float a = S * (float)((kx * h) & 255);
        v = dd ? -sinf(a) : cosf(a);
        hi = d_FH2hi; lo = d_FH2lo; idx = r;
    } else if (id < 163840) {                  // FHI2 [h][2kxIdx+d]
        int r = id - 98304; int h = r >> 8, q = r & 255;
        int kxi = q >> 1, dd = q & 1;
        int kx = (kxi < 64) ? kxi : kxi + 128;
        float a = S * (float)((kx * h) & 255);
        v = dd ? sinf(a) : cosf(a);
        hi = d_FHI2hi; lo = d_FHI2lo; idx = r;
    } else {                                   // FIW2 [2ky+c][w]
        int r = id - 163840; int n = r >> 8, w = r & 255; int ky = n >> 1;
        float s = ((ky == 0) ? 1.f : 2.f) * (1.f / 65536.f);
        float a = S * (float)((ky * w) & 255);
        v = (n & 1) ? -s * sinf(a) : s * cosf(a);
        hi = d_FIW2hi; lo = d_FIW2lo; idx = r;
    }
    __nv_bfloat16 h16 = __float2bfloat16(v);
    hi[idx] = h16;
    lo[idx] = __float2bfloat16(v - __bfloat162float(h16));
}

__global__ void init_wt_k(const float* __restrict__ w1re, const float* __restrict__ w1im,
                          const float* __restrict__ w2re, const float* __restrict__ w2im) {
    int id = blockIdx.x * 256 + threadIdx.x;
    if (id >= 2 * 256 * 4096) return;
    int t = id >> 20, rem = id & 1048575;
    int p = rem >> 12, io = rem & 4095;
    int i = io >> 6, o = io & 63;
    const float* re = t ? w2re : w1re;
    const float* im = t ? w2im : w1im;
    size_t src = ((size_t)(i * 64 + o)) * 256 + p;
    d_wt[id] = make_float2(re[src], im[src]);
}

__global__ void init_lbt_k(const float* __restrict__ b1re, const float* __restrict__ b1im,
                           const float* __restrict__ b2re, const float* __restrict__ b2im) {
    int id = blockIdx.x * 256 + threadIdx.x;
    if (id >= 2 * 15 * 256 * 256) return;
    int t = id / 983040, rem = id % 983040;
    int e = rem >> 16, rem2 = rem & 65535;
    int p = rem2 >> 8, ro = rem2 & 255;
    int r = ro >> 6, o = ro & 63;
    const float* re = t ? b2re : b1re;
    const float* im = t ? b2im : b1im;
    size_t src = (((size_t)(e * 64 + o)) * 4 + r) * 256 + p;
    d_lbt[id] = make_float2(re[src], im[src]);
}

__global__ void init_small_k(const float* __restrict__ la1re, const float* __restrict__ la1im,
                             const float* __restrict__ la2re, const float* __restrict__ la2im,
                             const float* __restrict__ g1, const float* __restrict__ g2,
                             float* sp_out) {
    int tid = threadIdx.x;
    for (int id = tid; id < 7680; id += 256) {
        int t = id / 3840, rem = id % 3840;
        const float* re = t ? la2re : la1re;
        const float* im = t ? la2im : la1im;
        d_la[id] = make_float2(re[rem], im[rem]);
    }
    __shared__ float gs[30];
    if (tid < 30) {
        float v = (tid < 15) ? g1[tid] : g2[tid - 15];
        float s = 1.0f / (1.0f + expf(-v));
        d_gate[tid] = s; gs[tid] = s;
    }
    __syncthreads();
    if (tid == 0 && sp_out) {
        float s = 0.0f;
        for (int i = 0; i < 30; i++) s += gs[i];
        *sp_out = s / 15.0f;
    }
}

// ---------------- unified bf16-split tensor-core GEMM ----------------
// BM=128, BN=128, BK=32, 512 threads (16 warps, 4x4), warp tile 32x32.
// STAGE 0: C = x * FW2            -> BpH/L      (M=131072, K=256, N=128)
// STAGE 1: C = FH2 * dup(Bp[bc])  -> Xf         (M=128,    K=512, N=128)
// STAGE 2: C = FHI2 * dup(Of[bo]) -> ZH/L       (M=256,    K=256, N=128)
// STAGE 3: C = Z * FIW2           -> out        (M=131072, K=128, N=256)
template<int STAGE, int KDIM, int LDB>
__global__ __launch_bounds__(512) void mma_gemm_k(const float* __restrict__ xin,
                                                  float* __restrict__ yout) {
    constexpr bool AFP32 = (STAGE == 0);
    constexpr bool BEXP  = (STAGE == 1 || STAGE == 2);
    __shared__ __align__(16) __nv_bfloat16 Ah[128*40], Al[128*40], Bh[32*136], Bl[32*136];
    int tid = threadIdx.x, lane = tid & 31, warp = tid >> 5;
    int mw = (warp >> 2) * 32, nw = (warp & 3) * 32;
    int g = lane >> 3, lr = lane & 7;
    int f_row = (g & 1) * 8 + lr;
    int f_col = (g >> 1) * 8;

    int m0 = 0, n0 = 0, bat = 0;
    if constexpr (STAGE == 0) { m0 = blockIdx.x * 128; }
    if constexpr (STAGE == 1) { bat = blockIdx.x; }
    if constexpr (STAGE == 2) { bat = blockIdx.x; m0 = blockIdx.y * 128; }
    if constexpr (STAGE == 3) { m0 = blockIdx.x * 128; n0 = blockIdx.y * 128; }

    const __nv_bfloat16 *AhG = nullptr, *AlG = nullptr, *BhG = nullptr, *BlG = nullptr;
    size_t boff = 0;
    if constexpr (STAGE == 0) { BhG = d_FW2hi;  BlG = d_FW2lo; }
    if constexpr (STAGE == 1) { AhG = d_FH2hi;  AlG = d_FH2lo;  BhG = d_BpH; BlG = d_BpL; boff = (size_t)bat * 32768; }
    if constexpr (STAGE == 2) { AhG = d_FHI2hi; AlG = d_FHI2lo; BhG = d_OfH; BlG = d_OfL; boff = (size_t)bat * 16384; }
    if constexpr (STAGE == 3) { AhG = d_ZH;     AlG = d_ZL;     BhG = d_FIW2hi; BlG = d_FIW2lo; }

    float c[2][4][4] = {};
    uint32_t sAh = (uint32_t)__cvta_generic_to_shared(Ah);
    uint32_t sAl = (uint32_t)__cvta_generic_to_shared(Al);
    uint32_t sBh = (uint32_t)__cvta_generic_to_shared(Bh);
    uint32_t sBl = (uint32_t)__cvta_generic_to_shared(Bl);

#pragma unroll 2
    for (int k0 = 0; k0 < KDIM; k0 += 32) {
        {   // A tile [128][32]
            int row = tid >> 2, cb = (tid & 3) * 8;
            if constexpr (AFP32) {
                const float* ap = xin + (size_t)(m0 + row) * KDIM + k0 + cb;
                float4 v0 = ((const float4*)ap)[0], v1 = ((const float4*)ap)[1];
                __nv_bfloat162 h0, l0, h1, l1, h2, l2, h3, l3;
                split2(v0.x, v0.y, h0, l0); split2(v0.z, v0.w, h1, l1);
                split2(v1.x, v1.y, h2, l2); split2(v1.z, v1.w, h3, l3);
                int o = row * 40 + cb;
                *(__nv_bfloat162*)&Ah[o]     = h0; *(__nv_bfloat162*)&Ah[o + 2] = h1;
                *(__nv_bfloat162*)&Ah[o + 4] = h2; *(__nv_bfloat162*)&Ah[o + 6] = h3;
                *(__nv_bfloat162*)&Al[o]     = l0; *(__nv_bfloat162*)&Al[o + 2] = l1;
                *(__nv_bfloat162*)&Al[o + 4] = l2; *(__nv_bfloat162*)&Al[o + 6] = l3;
            } else {
                size_t src = (size_t)(m0 + row) * KDIM + k0 + cb;
                *(uint4*)&Ah[row * 40 + cb] = *(const uint4*)(AhG + src);
                *(uint4*)&Al[row * 40 + cb] = *(const uint4*)(AlG + src);
            }
        }
        {   // B tile [32][128]
            int row = tid >> 4, cb = (tid & 15) * 8;
            if constexpr (BEXP) {
                int k = k0 + row, h = k >> 1, d = k & 1;
                const uint32_t* sh = (const uint32_t*)(BhG + boff + (size_t)h * 128 + cb);
                const uint32_t* sl = (const uint32_t*)(BlG + boff + (size_t)h * 128 + cb);
                uint32_t* dh = (uint32_t*)&Bh[row * 136 + cb];
                uint32_t* dl = (uint32_t*)&Bl[row * 136 + cb];
#pragma unroll
                for (int i = 0; i < 4; i++) {
                    uint32_t uh = sh[i], ul = sl[i];
                    if (d) {    // (re,im) -> (-im, re)
                        uh = (uh << 16) | ((uh >> 16) ^ 0x8000u);
                        ul = (ul << 16) | ((ul >> 16) ^ 0x8000u);
                    }
                    dh[i] = uh; dl[i] = ul;
                }
            } else {
                size_t src = (size_t)(k0 + row) * LDB + n0 + cb;
                *(uint4*)&Bh[row * 136 + cb] = *(const uint4*)(BhG + src);
                *(uint4*)&Bl[row * 136 + cb] = *(const uint4*)(BlG + src);
            }
        }
        __syncthreads();
#pragma unroll
        for (int ks = 0; ks < 2; ks++) {
            int koff = ks * 16;
            uint32_t ah[2][4], al[2][4];
#pragma unroll
            for (int mi = 0; mi < 2; mi++) {
                uint32_t off = (uint32_t)(((mw + mi * 16 + f_row) * 40 + koff + f_col) * 2);
                ldsm4(sAh + off, ah[mi][0], ah[mi][1], ah[mi][2], ah[mi][3]);
                ldsm4(sAl + off, al[mi][0], al[mi][1], al[mi][2], al[mi][3]);
            }
            uint32_t bh[4][2], bl[4][2];
#pragma unroll
            for (int p = 0; p < 2; p++) {
                uint32_t off = (uint32_t)(((koff + f_row) * 136 + nw + p * 16 + f_col) * 2);
                uint32_t r0, r1, r2, r3;
                ldsm4t(sBh + off, r0, r1, r2, r3);
                bh[2*p][0] = r0; bh[2*p][1] = r1; bh[2*p+1][0] = r2; bh[2*p+1][1] = r3;
                ldsm4t(sBl + off, r0, r1, r2, r3);
                bl[2*p][0] = r0; bl[2*p][1] = r1; bl[2*p+1][0] = r2; bl[2*p+1][1] = r3;
            }
#pragma unroll
            for (int mi = 0; mi < 2; mi++)
#pragma unroll
                for (int ni = 0; ni < 4; ni++) {
                    mma16816(c[mi][ni], ah[mi], bh[ni]);
                    mma16816(c[mi][ni], ah[mi], bl[ni]);
                    mma16816(c[mi][ni], al[mi], bh[ni]);
                }
        }
        __syncthreads();
    }
    // epilogue
#pragma unroll
    for (int mi = 0; mi < 2; mi++)
#pragma unroll
        for (int ni = 0; ni < 4; ni++) {
            int gm = m0 + mw + mi * 16 + (lane >> 2);
            int gn = n0 + nw + ni * 8 + (lane & 3) * 2;
            float v0 = c[mi][ni][0], v1 = c[mi][ni][1];
            float v2 = c[mi][ni][2], v3 = c[mi][ni][3];
            if constexpr (STAGE == 0) {
                store_split2(d_BpH, d_BpL, (size_t)gm * 128 + gn, v0, v1);
                store_split2(d_BpH, d_BpL, (size_t)(gm + 8) * 128 + gn, v2, v3);
            } else if constexpr (STAGE == 1) {
                float2* C2 = d_Xf + (size_t)bat * 8192;
                C2[gm * 64 + (gn >> 1)]       = make_float2(v0, v1);
                C2[(gm + 8) * 64 + (gn >> 1)] = make_float2(v2, v3);
            } else if constexpr (STAGE == 2) {
                size_t zb = (size_t)bat * 32768;
                store_split2(d_ZH, d_ZL, zb + (size_t)gm * 128 + gn, v0, v1);
                store_split2(d_ZH, d_ZL, zb + (size_t)(gm + 8) * 128 + gn, v2, v3);
            } else {
                float2* C2 = (float2*)yout;
                C2[(size_t)gm * 128 + (gn >> 1)]       = make_float2(v0, v1);
                C2[(size_t)(gm + 8) * 128 + (gn >> 1)] = make_float2(v2, v3);
            }
        }
}

// ---------------- spectral multiply (fp32; split-store to Of) ----------------
__global__ __launch_bounds__(512) void base_mul_k() {
    int t = blockIdx.x, p = blockIdx.y;
    int x = p >> 4, y = p & 15;
    int kxIdx = (t == 0) ? x : (112 + x);
    int ky = y;
    __shared__ float2 Xs[8][64];
    int tid = threadIdx.x;
    {
        int b = tid >> 6, i = tid & 63;
        Xs[b][i] = d_Xf[(size_t)(b * 64 + i) * 8192 + kxIdx * 64 + ky];
    }
    __syncthreads();
    int o = tid & 63, b = tid >> 6;
    const float2* wp = d_wt + ((size_t)t * 256 + p) * 4096;
    float2 s = {0.f, 0.f};
#pragma unroll 8
    for (int i = 0; i < 64; i++) cfma(s, Xs[b][i], wp[i * 64 + o]);
    size_t idx = (size_t)(b * 64 + o) * 16384 + (size_t)kxIdx * 128 + 2 * ky;
    store_split2(d_OfH, d_OfL, idx, s.x, s.y);
}

__global__ __launch_bounds__(512) void expert_mul_k() {
    int tile = blockIdx.x;
    int half = tile / 15, e = tile % 15;
    int p = blockIdx.y;
    int x = p >> 4, y = p & 15;
    int Rr = (e + 1) >> 2, Cc = (e + 1) & 3;
    int ky = Cc * 16 + y;
    int kxIdx = (half == 0) ? (Rr * 16 + x) : (64 + (3 - Rr) * 16 + x);
    __shared__ float2 Xs[8][64];
    __shared__ float2 Ts[8][4];
    int tid = threadIdx.x;
    {
        int b = tid >> 6, i = tid & 63;
        Xs[b][i] = d_Xf[(size_t)(b * 64 + i) * 8192 + kxIdx * 64 + ky];
    }
    __syncthreads();
    if (tid < 32) {
        int b = tid >> 2, r = tid & 3;
        const float2* lap = d_la + (size_t)(half * 15 + e) * 256 + r * 64;
        float2 s = {0.f, 0.f};
#pragma unroll 8
        for (int i = 0; i < 64; i++) cfma(s, Xs[b][i], lap[i]);
        Ts[b][r] = s;
    }
    __syncthreads();
    int o = tid & 63, b = tid >> 6;
    const float2* lbp = d_lbt + ((size_t)(half * 15 + e) * 256 + p) * 256;
    float2 s = {0.f, 0.f};
#pragma unroll
    for (int r = 0; r < 4; r++) cfma(s, Ts[b][r], lbp[r * 64 + o]);
    float gsc = d_gate[half * 15 + e] * 0.1f;
    s.x *= gsc; s.y *= gsc;
    size_t idx = (size_t)(b * 64 + o) * 16384 + (size_t)kxIdx * 128 + 2 * ky;
    store_split2(d_OfH, d_OfL, idx, s.x, s.y);
}

// ---------------------------------- launch ----------------------------------
extern "C" void kernel_launch(void* const* d_in, const int* in_sizes, int n_in,
                              void* d_out, int out_size) {
    const float* x     = (const float*)d_in[0];
    const float* w1re  = (const float*)d_in[1];
    const float* w1im  = (const float*)d_in[2];
    const float* w2re  = (const float*)d_in[3];
    const float* w2im  = (const float*)d_in[4];
    const float* la1re = (const float*)d_in[5];
    const float* la1im = (const float*)d_in[6];
    const float* lb1re = (const float*)d_in[7];
    const float* lb1im = (const float*)d_in[8];
    const float* la2re = (const float*)d_in[9];
    const float* la2im = (const float*)d_in[10];
    const float* lb2re = (const float*)d_in[11];
    const float* lb2im = (const float*)d_in[12];
    const float* g1    = (const float*)d_in[13];
    const float* g2    = (const float*)d_in[14];
    float* out = (float*)d_out;

    float* sp_out = (out_size > NTOT) ? (out + NTOT) : nullptr;

    init_tabs2_k<<<768, 256>>>();
    init_wt_k<<<8192, 256>>>(w1re, w1im, w2re, w2im);
    init_lbt_k<<<7680, 256>>>(lb1re, lb1im, lb2re, lb2im);
    init_small_k<<<1, 256>>>(la1re, la1im, la2re, la2im, g1, g2, sp_out);

    // K1: rfft along W -> Bp (bf16 hi/lo)
    mma_gemm_k<0, 256, 128><<<dim3(1024), 512>>>(x, nullptr);
    // K2: fwd H (dup rows built in B-loader) -> Xf
    mma_gemm_k<1, 512, 128><<<dim3(512), 512>>>(nullptr, nullptr);
    // spectral multiply (fp32 -> Of bf16 hi/lo)
    base_mul_k<<<dim3(2, 256), 512>>>();
    expert_mul_k<<<dim3(30, 256), 512>>>();
    // K5: inv H -> Z (bf16 hi/lo)
    mma_gemm_k<2, 256, 128><<<dim3(512, 2), 512>>>(nullptr, nullptr);
    // K6: irfft along W -> out
    mma_gemm_k<3, 128, 256><<<dim3(1024, 2), 512>>>(nullptr, out);
}

// round 13
// speedup vs baseline: 2.0593x; 1.1587x over previous
#include <cuda_runtime.h>
#include <cuda_bf16.h>
#include <math.h>
#include <stdint.h>

#define NTOT (8*64*256*256)

// ---------------- scratch ----------------
__device__ __nv_bfloat16 d_BpH[512*256*128], d_BpL[512*256*128];  // K1 out [bc][h][2ky+c]
__device__ float2        d_Xf [512*128*64];                       // x_ft corners [bc][kx][ky]
__device__ __nv_bfloat16 d_OfH[512*128*128], d_OfL[512*128*128];  // spectral out [bo][kx][2ky+c]
__device__ __nv_bfloat16 d_ZH [512*256*128], d_ZL [512*256*128];  // inv-H out [bo][h][2ky+c]
// bf16-split twiddle tables
__device__ __nv_bfloat16 d_FW2hi [256*128], d_FW2lo [256*128];
__device__ __nv_bfloat16 d_FH2hi [128*512], d_FH2lo [128*512];
__device__ __nv_bfloat16 d_FHI2hi[256*256], d_FHI2lo[256*256];
__device__ __nv_bfloat16 d_FIW2hi[128*256], d_FIW2lo[128*256];
// spectral weights
__device__ float2 d_wt [2*256*64*64];
__device__ float2 d_lbt[2*15*256*4*64];
__device__ float2 d_la [2*15*4*64];
__device__ float  d_gate[30];

__device__ __forceinline__ void cfma(float2& c, float2 a, float2 b) {
    c.x = fmaf(a.x, b.x, c.x); c.x = fmaf(-a.y, b.y, c.x);
    c.y = fmaf(a.x, b.y, c.y); c.y = fmaf( a.y, b.x, c.y);
}

__device__ __forceinline__ void split2(float a, float b, __nv_bfloat162& h, __nv_bfloat162& l) {
    __nv_bfloat16 ha = __float2bfloat16(a), hb = __float2bfloat16(b);
    h.x = ha; h.y = hb;
    l.x = __float2bfloat16(a - __bfloat162float(ha));
    l.y = __float2bfloat16(b - __bfloat162float(hb));
}

__device__ __forceinline__ void store_split2(__nv_bfloat16* H, __nv_bfloat16* L,
                                             size_t idx, float a, float b) {
    __nv_bfloat162 h, l; split2(a, b, h, l);
    *(__nv_bfloat162*)(H + idx) = h;
    *(__nv_bfloat162*)(L + idx) = l;
}

__device__ __forceinline__ void ldsm4(uint32_t addr, uint32_t& r0, uint32_t& r1, uint32_t& r2, uint32_t& r3) {
    asm volatile("ldmatrix.sync.aligned.m8n8.x4.shared.b16 {%0,%1,%2,%3}, [%4];"
                 : "=r"(r0), "=r"(r1), "=r"(r2), "=r"(r3) : "r"(addr));
}
__device__ __forceinline__ void ldsm4t(uint32_t addr, uint32_t& r0, uint32_t& r1, uint32_t& r2, uint32_t& r3) {
    asm volatile("ldmatrix.sync.aligned.m8n8.x4.trans.shared.b16 {%0,%1,%2,%3}, [%4];"
                 : "=r"(r0), "=r"(r1), "=r"(r2), "=r"(r3) : "r"(addr));
}
__device__ __forceinline__ void mma16816(float* c, const uint32_t* a, const uint32_t* b) {
    asm volatile("mma.sync.aligned.m16n8k16.row.col.f32.bf16.bf16.f32 "
                 "{%0,%1,%2,%3},{%4,%5,%6,%7},{%8,%9},{%0,%1,%2,%3};"
                 : "+f"(c[0]), "+f"(c[1]), "+f"(c[2]), "+f"(c[3])
                 : "r"(a[0]), "r"(a[1]), "r"(a[2]), "r"(a[3]), "r"(b[0]), "r"(b[1]));
}

// ---------------- table init ----------------
__global__ void init_tabs2_k() {
    int id = blockIdx.x * 256 + threadIdx.x;   // 196608 total
    const float S = 6.283185307179586f / 256.0f;
    float v; __nv_bfloat16 *hi, *lo; int idx;
    if (id < 32768) {                          // FW2 [w][2ky+c]
        int w = id >> 7, n = id & 127, ky = n >> 1;
        float a = S * (float)((w * ky) & 255);
        v = (n & 1) ? -sinf(a) : cosf(a);
        hi = d_FW2hi; lo = d_FW2lo; idx = id;
    } else if (id < 98304) {                   // FH2 [kxIdx][2h+d]
        int r = id - 32768; int m = r >> 9, q = r & 511;
        int h = q >> 1, dd = q & 1;
        int kx = (m < 64) ? m : m + 128;
        float a = S * (float)((kx * h) & 255);
        v = dd ? -sinf(a) : cosf(a);
        hi = d_FH2hi; lo = d_FH2lo; idx = r;
    } else if (id < 163840) {                  // FHI2 [h][2kxIdx+d]
        int r = id - 98304; int h = r >> 8, q = r & 255;
        int kxi = q >> 1, dd = q & 1;
        int kx = (kxi < 64) ? kxi : kxi + 128;
        float a = S * (float)((kx * h) & 255);
        v = dd ? sinf(a) : cosf(a);
        hi = d_FHI2hi; lo = d_FHI2lo; idx = r;
    } else {                                   // FIW2 [2ky+c][w]
        int r = id - 163840; int n = r >> 8, w = r & 255; int ky = n >> 1;
        float s = ((ky == 0) ? 1.f : 2.f) * (1.f / 65536.f);
        float a = S * (float)((ky * w) & 255);
        v = (n & 1) ? -s * sinf(a) : s * cosf(a);
        hi = d_FIW2hi; lo = d_FIW2lo; idx = r;
    }
    __nv_bfloat16 h16 = __float2bfloat16(v);
    hi[idx] = h16;
    lo[idx] = __float2bfloat16(v - __bfloat162float(h16));
}

__global__ void init_wt_k(const float* __restrict__ w1re, const float* __restrict__ w1im,
                          const float* __restrict__ w2re, const float* __restrict__ w2im) {
    int id = blockIdx.x * 256 + threadIdx.x;
    if (id >= 2 * 256 * 4096) return;
    int t = id >> 20, rem = id & 1048575;
    int p = rem >> 12, io = rem & 4095;
    int i = io >> 6, o = io & 63;
    const float* re = t ? w2re : w1re;
    const float* im = t ? w2im : w1im;
    size_t src = ((size_t)(i * 64 + o)) * 256 + p;
    d_wt[id] = make_float2(re[src], im[src]);
}

__global__ void init_lbt_k(const float* __restrict__ b1re, const float* __restrict__ b1im,
                           const float* __restrict__ b2re, const float* __restrict__ b2im) {
    int id = blockIdx.x * 256 + threadIdx.x;
    if (id >= 2 * 15 * 256 * 256) return;
    int t = id / 983040, rem = id % 983040;
    int e = rem >> 16, rem2 = rem & 65535;
    int p = rem2 >> 8, ro = rem2 & 255;
    int r = ro >> 6, o = ro & 63;
    const float* re = t ? b2re : b1re;
    const float* im = t ? b2im : b1im;
    size_t src = (((size_t)(e * 64 + o)) * 4 + r) * 256 + p;
    d_lbt[id] = make_float2(re[src], im[src]);
}

__global__ void init_small_k(const float* __restrict__ la1re, const float* __restrict__ la1im,
                             const float* __restrict__ la2re, const float* __restrict__ la2im,
                             const float* __restrict__ g1, const float* __restrict__ g2,
                             float* sp_out) {
    int tid = threadIdx.x;
    for (int id = tid; id < 7680; id += 256) {
        int t = id / 3840, rem = id % 3840;
        const float* re = t ? la2re : la1re;
        const float* im = t ? la2im : la1im;
        d_la[id] = make_float2(re[rem], im[rem]);
    }
    __shared__ float gs[30];
    if (tid < 30) {
        float v = (tid < 15) ? g1[tid] : g2[tid - 15];
        float s = 1.0f / (1.0f + expf(-v));
        d_gate[tid] = s; gs[tid] = s;
    }
    __syncthreads();
    if (tid == 0 && sp_out) {
        float s = 0.0f;
        for (int i = 0; i < 30; i++) s += gs[i];
        *sp_out = s / 15.0f;
    }
}

// ---------------- unified bf16-split tensor-core GEMM, double-buffered ----------------
// BM=128, BN=128, BK=32, 512 threads (16 warps, 4x4), warp tile 32x32.
// STAGE 0: C = x * FW2            -> BpH/L      (M=131072, K=256, N=128)
// STAGE 1: C = FH2 * dup(Bp[bc])  -> Xf         (M=128,    K=512, N=128)
// STAGE 2: C = FHI2 * dup(Of[bo]) -> ZH/L       (M=256,    K=256, N=128)
// STAGE 3: C = Z * FIW2           -> out        (M=131072, K=128, N=256)
#define ASZ  (128*40)
#define BSZ  (32*136)
#define ASZB (ASZ*2)
#define BSZB (BSZ*2)
#define BUFE (2*ASZ + 2*BSZ)
#define BUFB (BUFE*2)
#define SMEM_BYTES (2*BUFB)

template<int STAGE, int KDIM, int LDB>
__global__ __launch_bounds__(512) void mma_gemm_k(const float* __restrict__ xin,
                                                  float* __restrict__ yout) {
    constexpr bool AFP32 = (STAGE == 0);
    constexpr bool BEXP  = (STAGE == 1 || STAGE == 2);
    constexpr int NI = KDIM / 32;
    extern __shared__ __align__(16) __nv_bfloat16 smem[];
    int tid = threadIdx.x, lane = tid & 31, warp = tid >> 5;
    int mw = (warp >> 2) * 32, nw = (warp & 3) * 32;
    int g = lane >> 3, lr = lane & 7;
    int f_row = (g & 1) * 8 + lr;
    int f_col = (g >> 1) * 8;

    int m0 = 0, n0 = 0, bat = 0;
    if constexpr (STAGE == 0) { m0 = blockIdx.x * 128; }
    if constexpr (STAGE == 1) { bat = blockIdx.x; }
    if constexpr (STAGE == 2) { bat = blockIdx.x; m0 = blockIdx.y * 128; }
    if constexpr (STAGE == 3) { m0 = blockIdx.x * 128; n0 = blockIdx.y * 128; }

    const __nv_bfloat16 *AhG = nullptr, *AlG = nullptr, *BhG = nullptr, *BlG = nullptr;
    size_t boff = 0;
    if constexpr (STAGE == 0) { BhG = d_FW2hi;  BlG = d_FW2lo; }
    if constexpr (STAGE == 1) { AhG = d_FH2hi;  AlG = d_FH2lo;  BhG = d_BpH; BlG = d_BpL; boff = (size_t)bat * 32768; }
    if constexpr (STAGE == 2) { AhG = d_FHI2hi; AlG = d_FHI2lo; BhG = d_OfH; BlG = d_OfL; boff = (size_t)bat * 16384; }
    if constexpr (STAGE == 3) { AhG = d_ZH;     AlG = d_ZL;     BhG = d_FIW2hi; BlG = d_FIW2lo; }

    int arow = tid >> 2, acb = (tid & 3) * 8;
    int brow = tid >> 4, bcb = (tid & 15) * 8;
    int bdup = brow & 1;                       // BEXP: k parity is per-thread constant

    float c[2][4][4] = {};
    uint32_t sbase = (uint32_t)__cvta_generic_to_shared(smem);

    uint4 pa0, pa1, pb0, pb1;                  // prefetch registers

    // ---- tile loaders (global -> regs) ----
    auto loadT = [&](int k0, uint4& a0, uint4& a1, uint4& b0, uint4& b1) {
        if constexpr (AFP32) {
            const float* ap = xin + (size_t)(m0 + arow) * KDIM + k0 + acb;
            a0 = ((const uint4*)ap)[0]; a1 = ((const uint4*)ap)[1];
        } else {
            size_t src = (size_t)(m0 + arow) * KDIM + k0 + acb;
            a0 = *(const uint4*)(AhG + src);
            a1 = *(const uint4*)(AlG + src);
        }
        if constexpr (BEXP) {
            int h = (k0 + brow) >> 1;
            b0 = *(const uint4*)(BhG + boff + (size_t)h * 128 + bcb);
            b1 = *(const uint4*)(BlG + boff + (size_t)h * 128 + bcb);
        } else {
            size_t src = (size_t)(k0 + brow) * LDB + n0 + bcb;
            b0 = *(const uint4*)(BhG + src);
            b1 = *(const uint4*)(BlG + src);
        }
    };
    // ---- regs -> smem buffer (with conversion) ----
    auto storeT = [&](int buf, uint4 a0, uint4 a1, uint4 b0, uint4 b1) {
        __nv_bfloat16* Ah = smem + buf * BUFE;
        __nv_bfloat16* Al = Ah + ASZ;
        __nv_bfloat16* Bh = Al + ASZ;
        __nv_bfloat16* Bl = Bh + BSZ;
        if constexpr (AFP32) {
            float4 v0 = *(float4*)&a0, v1 = *(float4*)&a1;
            __nv_bfloat162 h0, l0, h1, l1, h2, l2, h3, l3;
            split2(v0.x, v0.y, h0, l0); split2(v0.z, v0.w, h1, l1);
            split2(v1.x, v1.y, h2, l2); split2(v1.z, v1.w, h3, l3);
            int o = arow * 40 + acb;
            *(__nv_bfloat162*)&Ah[o]     = h0; *(__nv_bfloat162*)&Ah[o + 2] = h1;
            *(__nv_bfloat162*)&Ah[o + 4] = h2; *(__nv_bfloat162*)&Ah[o + 6] = h3;
            *(__nv_bfloat162*)&Al[o]     = l0; *(__nv_bfloat162*)&Al[o + 2] = l1;
            *(__nv_bfloat162*)&Al[o + 4] = l2; *(__nv_bfloat162*)&Al[o + 6] = l3;
        } else {
            *(uint4*)&Ah[arow * 40 + acb] = a0;
            *(uint4*)&Al[arow * 40 + acb] = a1;
        }
        if constexpr (BEXP) {
            uint32_t* dh = (uint32_t*)&Bh[brow * 136 + bcb];
            uint32_t* dl = (uint32_t*)&Bl[brow * 136 + bcb];
            const uint32_t* sh = (const uint32_t*)&b0;
            const uint32_t* sl = (const uint32_t*)&b1;
#pragma unroll
            for (int i = 0; i < 4; i++) {
                uint32_t uh = sh[i], ul = sl[i];
                if (bdup) {    // (re,im) -> (-im, re)
                    uh = (uh << 16) | ((uh >> 16) ^ 0x8000u);
                    ul = (ul << 16) | ((ul >> 16) ^ 0x8000u);
                }
                dh[i] = uh; dl[i] = ul;
            }
        } else {
            *(uint4*)&Bh[brow * 136 + bcb] = b0;
            *(uint4*)&Bl[brow * 136 + bcb] = b1;
        }
    };

    loadT(0, pa0, pa1, pb0, pb1);
    storeT(0, pa0, pa1, pb0, pb1);
    __syncthreads();

#pragma unroll 1
    for (int i = 0; i < NI; i++) {
        int cur = i & 1;
        bool more = (i + 1 < NI);
        if (more) loadT((i + 1) * 32, pa0, pa1, pb0, pb1);

        uint32_t sAh = sbase + cur * BUFB;
        uint32_t sAl = sAh + ASZB;
        uint32_t sBh = sAl + ASZB;
        uint32_t sBl = sBh + BSZB;
#pragma unroll
        for (int ks = 0; ks < 2; ks++) {
            int koff = ks * 16;
            uint32_t ah[2][4], al[2][4];
#pragma unroll
            for (int mi = 0; mi < 2; mi++) {
                uint32_t off = (uint32_t)(((mw + mi * 16 + f_row) * 40 + koff + f_col) * 2);
                ldsm4(sAh + off, ah[mi][0], ah[mi][1], ah[mi][2], ah[mi][3]);
                ldsm4(sAl + off, al[mi][0], al[mi][1], al[mi][2], al[mi][3]);
            }
            uint32_t bh[4][2], bl[4][2];
#pragma unroll
            for (int p = 0; p < 2; p++) {
                uint32_t off = (uint32_t)(((koff + f_row) * 136 + nw + p * 16 + f_col) * 2);
                uint32_t r0, r1, r2, r3;
                ldsm4t(sBh + off, r0, r1, r2, r3);
                bh[2*p][0] = r0; bh[2*p][1] = r1; bh[2*p+1][0] = r2; bh[2*p+1][1] = r3;
                ldsm4t(sBl + off, r0, r1, r2, r3);
                bl[2*p][0] = r0; bl[2*p][1] = r1; bl[2*p+1][0] = r2; bl[2*p+1][1] = r3;
            }
#pragma unroll
            for (int mi = 0; mi < 2; mi++)
#pragma unroll
                for (int ni = 0; ni < 4; ni++) {
                    mma16816(c[mi][ni], ah[mi], bh[ni]);
                    mma16816(c[mi][ni], ah[mi], bl[ni]);
                    mma16816(c[mi][ni], al[mi], bh[ni]);
                }
        }
        if (more) storeT(1 - cur, pa0, pa1, pb0, pb1);
        __syncthreads();
    }

    // epilogue
#pragma unroll
    for (int mi = 0; mi < 2; mi++)
#pragma unroll
        for (int ni = 0; ni < 4; ni++) {
            int gm = m0 + mw + mi * 16 + (lane >> 2);
            int gn = n0 + nw + ni * 8 + (lane & 3) * 2;
            float v0 = c[mi][ni][0], v1 = c[mi][ni][1];
            float v2 = c[mi][ni][2], v3 = c[mi][ni][3];
            if constexpr (STAGE == 0) {
                store_split2(d_BpH, d_BpL, (size_t)gm * 128 + gn, v0, v1);
                store_split2(d_BpH, d_BpL, (size_t)(gm + 8) * 128 + gn, v2, v3);
            } else if constexpr (STAGE == 1) {
                float2* C2 = d_Xf + (size_t)bat * 8192;
                C2[gm * 64 + (gn >> 1)]       = make_float2(v0, v1);
                C2[(gm + 8) * 64 + (gn >> 1)] = make_float2(v2, v3);
            } else if constexpr (STAGE == 2) {
                size_t zb = (size_t)bat * 32768;
                store_split2(d_ZH, d_ZL, zb + (size_t)gm * 128 + gn, v0, v1);
                store_split2(d_ZH, d_ZL, zb + (size_t)(gm + 8) * 128 + gn, v2, v3);
            } else {
                float2* C2 = (float2*)yout;
                C2[(size_t)gm * 128 + (gn >> 1)]       = make_float2(v0, v1);
                C2[(size_t)(gm + 8) * 128 + (gn >> 1)] = make_float2(v2, v3);
            }
        }
}

// ---------------- spectral multiply (fp32; split-store to Of) ----------------
__global__ __launch_bounds__(512) void base_mul_k() {
    int t = blockIdx.x, p = blockIdx.y;
    int x = p >> 4, y = p & 15;
    int kxIdx = (t == 0) ? x : (112 + x);
    int ky = y;
    __shared__ float2 Xs[8][64];
    int tid = threadIdx.x;
    {
        int b = tid >> 6, i = tid & 63;
        Xs[b][i] = d_Xf[(size_t)(b * 64 + i) * 8192 + kxIdx * 64 + ky];
    }
    __syncthreads();
    int o = tid & 63, b = tid >> 6;
    const float2* wp = d_wt + ((size_t)t * 256 + p) * 4096;
    float2 s = {0.f, 0.f};
#pragma unroll 8
    for (int i = 0; i < 64; i++) cfma(s, Xs[b][i], wp[i * 64 + o]);
    size_t idx = (size_t)(b * 64 + o) * 16384 + (size_t)kxIdx * 128 + 2 * ky;
    store_split2(d_OfH, d_OfL, idx, s.x, s.y);
}

__global__ __launch_bounds__(512) void expert_mul_k() {
    int tile = blockIdx.x;
    int half = tile / 15, e = tile % 15;
    int p = blockIdx.y;
    int x = p >> 4, y = p & 15;
    int Rr = (e + 1) >> 2, Cc = (e + 1) & 3;
    int ky = Cc * 16 + y;
    int kxIdx = (half == 0) ? (Rr * 16 + x) : (64 + (3 - Rr) * 16 + x);
    __shared__ float2 Xs[8][64];
    __shared__ float2 Ts[8][4];
    int tid = threadIdx.x;
    {
        int b = tid >> 6, i = tid & 63;
        Xs[b][i] = d_Xf[(size_t)(b * 64 + i) * 8192 + kxIdx * 64 + ky];
    }
    __syncthreads();
    if (tid < 32) {
        int b = tid >> 2, r = tid & 3;
        const float2* lap = d_la + (size_t)(half * 15 + e) * 256 + r * 64;
        float2 s = {0.f, 0.f};
#pragma unroll 8
        for (int i = 0; i < 64; i++) cfma(s, Xs[b][i], lap[i]);
        Ts[b][r] = s;
    }
    __syncthreads();
    int o = tid & 63, b = tid >> 6;
    const float2* lbp = d_lbt + ((size_t)(half * 15 + e) * 256 + p) * 256;
    float2 s = {0.f, 0.f};
#pragma unroll
    for (int r = 0; r < 4; r++) cfma(s, Ts[b][r], lbp[r * 64 + o]);
    float gsc = d_gate[half * 15 + e] * 0.1f;
    s.x *= gsc; s.y *= gsc;
    size_t idx = (size_t)(b * 64 + o) * 16384 + (size_t)kxIdx * 128 + 2 * ky;
    store_split2(d_OfH, d_OfL, idx, s.x, s.y);
}

// ---------------------------------- launch ----------------------------------
extern "C" void kernel_launch(void* const* d_in, const int* in_sizes, int n_in,
                              void* d_out, int out_size) {
    const float* x     = (const float*)d_in[0];
    const float* w1re  = (const float*)d_in[1];
    const float* w1im  = (const float*)d_in[2];
    const float* w2re  = (const float*)d_in[3];
    const float* w2im  = (const float*)d_in[4];
    const float* la1re = (const float*)d_in[5];
    const float* la1im = (const float*)d_in[6];
    const float* lb1re = (const float*)d_in[7];
    const float* lb1im = (const float*)d_in[8];
    const float* la2re = (const float*)d_in[9];
    const float* la2im = (const float*)d_in[10];
    const float* lb2re = (const float*)d_in[11];
    const float* lb2im = (const float*)d_in[12];
    const float* g1    = (const float*)d_in[13];
    const float* g2    = (const float*)d_in[14];
    float* out = (float*)d_out;

    float* sp_out = (out_size > NTOT) ? (out + NTOT) : nullptr;

    static bool attr_set = false;
    if (!attr_set) {
        cudaFuncSetAttribute(mma_gemm_k<0, 256, 128>, cudaFuncAttributeMaxDynamicSharedMemorySize, SMEM_BYTES);
        cudaFuncSetAttribute(mma_gemm_k<1, 512, 128>, cudaFuncAttributeMaxDynamicSharedMemorySize, SMEM_BYTES);
        cudaFuncSetAttribute(mma_gemm_k<2, 256, 128>, cudaFuncAttributeMaxDynamicSharedMemorySize, SMEM_BYTES);
        cudaFuncSetAttribute(mma_gemm_k<3, 128, 256>, cudaFuncAttributeMaxDynamicSharedMemorySize, SMEM_BYTES);
        attr_set = true;
    }

    init_tabs2_k<<<768, 256>>>();
    init_wt_k<<<8192, 256>>>(w1re, w1im, w2re, w2im);
    init_lbt_k<<<7680, 256>>>(lb1re, lb1im, lb2re, lb2im);
    init_small_k<<<1, 256>>>(la1re, la1im, la2re, la2im, g1, g2, sp_out);

    // K1: rfft along W -> Bp (bf16 hi/lo)
    mma_gemm_k<0, 256, 128><<<dim3(1024), 512, SMEM_BYTES>>>(x, nullptr);
    // K2: fwd H (dup rows built at smem store) -> Xf
    mma_gemm_k<1, 512, 128><<<dim3(512), 512, SMEM_BYTES>>>(nullptr, nullptr);
    // spectral multiply (fp32 -> Of bf16 hi/lo)
    base_mul_k<<<dim3(2, 256), 512>>>();
    expert_mul_k<<<dim3(30, 256), 512>>>();
    // K5: inv H -> Z (bf16 hi/lo)
    mma_gemm_k<2, 256, 128><<<dim3(512, 2), 512, SMEM_BYTES>>>(nullptr, nullptr);
    // K6: irfft along W -> out
    mma_gemm_k<3, 128, 256><<<dim3(1024, 2), 512, SMEM_BYTES>>>(nullptr, out);
}